// round 8
// baseline (speedup 1.0000x reference)
#include <cuda_runtime.h>
#include <cuda_bf16.h>
#include <math.h>
#include <math_constants.h>
#include <cstdint>

// Problem constants
#define BB  2
#define TT  2048
#define DDIM 1024
#define HH  16
#define DHH 64
#define MM  (BB*TT)

// ---------------------------------------------------------------------------
// Scratch (device globals)
// ---------------------------------------------------------------------------
__device__ float g_v[(size_t)MM * DDIM];
__device__ float g_sin[TT * 32];
__device__ float g_cos[TT * 32];

__device__ __nv_bfloat16 g_ahi[(size_t)MM * DDIM];
__device__ __nv_bfloat16 g_alo[(size_t)MM * DDIM];
__device__ __nv_bfloat16 g_whi[(size_t)4 * DDIM * DDIM];
__device__ __nv_bfloat16 g_wlo[(size_t)4 * DDIM * DDIM];

// attention bf16 operands
__device__ __nv_bfloat16 g_qhi[(size_t)MM * DDIM];
__device__ __nv_bfloat16 g_qlo[(size_t)MM * DDIM];
__device__ __nv_bfloat16 g_khi[(size_t)MM * DDIM];
__device__ __nv_bfloat16 g_klo[(size_t)MM * DDIM];
__device__ __nv_bfloat16 g_vthi[(size_t)MM * DDIM];  // [b,h,dh,T]
__device__ __nv_bfloat16 g_vtlo[(size_t)MM * DDIM];

// ---------------------------------------------------------------------------
// Warp tensor helpers (baseline PTX: ldmatrix + mma.sync + cp.async)
// ---------------------------------------------------------------------------
__device__ __forceinline__ uint32_t smem_u32(const void* p) {
    uint32_t a;
    asm("{ .reg .u64 t; cvta.to.shared.u64 t, %1; cvt.u32.u64 %0, t; }"
        : "=r"(a) : "l"(p));
    return a;
}

__device__ __forceinline__ void ldm_x4(uint32_t* r, uint32_t addr) {
    asm volatile("ldmatrix.sync.aligned.m8n8.x4.shared.b16 {%0,%1,%2,%3}, [%4];"
                 : "=r"(r[0]), "=r"(r[1]), "=r"(r[2]), "=r"(r[3]) : "r"(addr));
}

__device__ __forceinline__ void mma16816(float* c, const uint32_t* a,
                                         const uint32_t* b) {
    asm volatile(
        "mma.sync.aligned.m16n8k16.row.col.f32.bf16.bf16.f32 "
        "{%0,%1,%2,%3}, {%4,%5,%6,%7}, {%8,%9}, {%0,%1,%2,%3};"
        : "+f"(c[0]), "+f"(c[1]), "+f"(c[2]), "+f"(c[3])
        : "r"(a[0]), "r"(a[1]), "r"(a[2]), "r"(a[3]), "r"(b[0]), "r"(b[1]));
}

__device__ __forceinline__ void cp16(uint32_t dst, const void* src) {
    asm volatile("cp.async.cg.shared.global [%0], [%1], 16;"
                 :: "r"(dst), "l"(src));
}
#define CP_COMMIT() asm volatile("cp.async.commit_group;" ::: "memory")
#define CP_WAIT0()  asm volatile("cp.async.wait_group 0;" ::: "memory")

__device__ __forceinline__ uint32_t cvt_bf2(float lo, float hi) {
    uint32_t r;
    asm("cvt.rn.bf16x2.f32 %0, %1, %2;" : "=r"(r) : "f"(hi), "f"(lo));
    return r;
}
__device__ __forceinline__ float2 unpack_bf2(uint32_t v) {
    __nv_bfloat162 b = *reinterpret_cast<__nv_bfloat162*>(&v);
    return __bfloat1622float2(b);
}

// ---------------------------------------------------------------------------
// RoPE sin/cos table
// ---------------------------------------------------------------------------
__global__ void sincos_kernel() {
    int idx = blockIdx.x * blockDim.x + threadIdx.x;
    if (idx >= TT * 32) return;
    int t  = idx >> 5;
    int jj = idx & 31;
    double ang = (double)t * pow(10000.0, -2.0 * (double)jj / 64.0);
    g_sin[idx] = (float)sin(ang);
    g_cos[idx] = (float)cos(ang);
}

// ---------------------------------------------------------------------------
// fp32 -> bf16 hi/lo split (vectorized)
// ---------------------------------------------------------------------------
__global__ void split_kernel(const float* __restrict__ src,
                             __nv_bfloat16* __restrict__ hi,
                             __nv_bfloat16* __restrict__ lo, int n4) {
    int i = blockIdx.x * blockDim.x + threadIdx.x;
    if (i >= n4) return;
    float4 v = ((const float4*)src)[i];
    __nv_bfloat16 h0 = __float2bfloat16(v.x), h1 = __float2bfloat16(v.y);
    __nv_bfloat16 h2 = __float2bfloat16(v.z), h3 = __float2bfloat16(v.w);
    uint2 hh, ll;
    hh.x = cvt_bf2(v.x, v.y); hh.y = cvt_bf2(v.z, v.w);
    ll.x = cvt_bf2(v.x - __bfloat162float(h0), v.y - __bfloat162float(h1));
    ll.y = cvt_bf2(v.z - __bfloat162float(h2), v.w - __bfloat162float(h3));
    ((uint2*)hi)[i] = hh;
    ((uint2*)lo)[i] = ll;
}

// fp32 W[K,N] -> bf16 hi/lo transposed [N,K]
__global__ void splitT_kernel(const float* __restrict__ w,
                              __nv_bfloat16* __restrict__ hi,
                              __nv_bfloat16* __restrict__ lo) {
    __shared__ float tile[32][33];
    int bx = blockIdx.x * 32;
    int by = blockIdx.y * 32;
    int tx = threadIdx.x, ty = threadIdx.y;
#pragma unroll
    for (int i = 0; i < 32; i += 8)
        tile[ty + i][tx] = w[(size_t)(by + ty + i) * DDIM + bx + tx];
    __syncthreads();
#pragma unroll
    for (int i = 0; i < 32; i += 8) {
        float v = tile[tx][ty + i];
        size_t o = (size_t)(bx + ty + i) * DDIM + by + tx;
        __nv_bfloat16 h = __float2bfloat16(v);
        hi[o] = h;
        lo[o] = __float2bfloat16(v - __bfloat162float(h));
    }
}

// ---------------------------------------------------------------------------
// Shared GEMM mainloop pieces
// ---------------------------------------------------------------------------
#define GT_ROW 80        // bytes per smem row (40 bf16)
#define GT_ARR 10240     // bytes per tile array (128*80)
#define GT_BUF 40960     // bytes per stage (4 arrays)
#define GEMM_SMEM (2 * GT_BUF)

#define G_LOAD(kt, buf) do {                                                  \
        int k0_ = (kt) * 32;                                                  \
        _Pragma("unroll")                                                     \
        for (int half = 0; half < 2; half++) {                                \
            int row_ = half * 64 + ld_row;                                    \
            size_t ga_ = (size_t)(bm + row_) * DDIM + k0_ + ld_cg;            \
            size_t gb_ = (size_t)(bn + row_) * DDIM + k0_ + ld_cg;            \
            uint32_t so_ = sb + (buf) * GT_BUF + row_ * GT_ROW + ld_cg * 2;   \
            cp16(so_ + 0 * GT_ARR, Ah + ga_);                                 \
            cp16(so_ + 1 * GT_ARR, Al + ga_);                                 \
            cp16(so_ + 2 * GT_ARR, Bh + gb_);                                 \
            cp16(so_ + 3 * GT_ARR, Bl + gb_);                                 \
        } } while (0)

// ---------------------------------------------------------------------------
// Tensor-core GEMM, cp.async double-buffered (bf16 3-pass split, fp32 accum)
// Block 128x128, 8 warps (warp tile 64x32), kTile=32.  fp32 output + bias.
// ---------------------------------------------------------------------------
__global__ void __launch_bounds__(256) mma_gemm(
    const __nv_bfloat16* __restrict__ Ah, const __nv_bfloat16* __restrict__ Al,
    const __nv_bfloat16* __restrict__ Bh, const __nv_bfloat16* __restrict__ Bl,
    const float* __restrict__ bias, float* __restrict__ C)
{
    extern __shared__ char gsm[];
    const uint32_t sb = smem_u32(gsm);

    const int tid = threadIdx.x;
    const int lane = tid & 31;
    const int wid = tid >> 5;
    const int wm = (wid & 1) * 64;
    const int wn = (wid >> 1) * 32;
    const int bn = blockIdx.x * 128;
    const int bm = blockIdx.y * 128;

    float acc[4][4][4];
#pragma unroll
    for (int i = 0; i < 4; i++)
#pragma unroll
        for (int j = 0; j < 4; j++)
#pragma unroll
            for (int r = 0; r < 4; r++) acc[i][j][r] = 0.f;

    const int a_row = lane & 15;
    const int a_kof = (lane >> 4) << 3;
    const int b_n   = (lane & 7) + ((lane >> 4) << 3);
    const int b_kof = ((lane >> 3) & 1) << 3;

    const int ld_row = tid >> 2;
    const int ld_cg  = (tid & 3) * 8;

    G_LOAD(0, 0);
    CP_COMMIT();

    for (int kt = 0; kt < 32; kt++) {
        CP_WAIT0();
        __syncthreads();
        if (kt + 1 < 32) { G_LOAD(kt + 1, (kt + 1) & 1); CP_COMMIT(); }

        const uint32_t bufb = sb + (kt & 1) * GT_BUF;
#pragma unroll
        for (int ko = 0; ko < 32; ko += 16) {
            uint32_t bh[4][2], bl[4][2];
#pragma unroll
            for (int p = 0; p < 2; p++) {
                uint32_t t4[4];
                uint32_t boff = (wn + p * 16 + b_n) * GT_ROW + (ko + b_kof) * 2;
                ldm_x4(t4, bufb + 2 * GT_ARR + boff);
                bh[p * 2][0] = t4[0]; bh[p * 2][1] = t4[1];
                bh[p * 2 + 1][0] = t4[2]; bh[p * 2 + 1][1] = t4[3];
                ldm_x4(t4, bufb + 3 * GT_ARR + boff);
                bl[p * 2][0] = t4[0]; bl[p * 2][1] = t4[1];
                bl[p * 2 + 1][0] = t4[2]; bl[p * 2 + 1][1] = t4[3];
            }
#pragma unroll
            for (int mf = 0; mf < 4; mf++) {
                uint32_t ahr[4], alr[4];
                uint32_t aoff = (wm + mf * 16 + a_row) * GT_ROW + (ko + a_kof) * 2;
                ldm_x4(ahr, bufb + 0 * GT_ARR + aoff);
                ldm_x4(alr, bufb + 1 * GT_ARR + aoff);
#pragma unroll
                for (int nf = 0; nf < 4; nf++) {
                    mma16816(acc[mf][nf], ahr, bh[nf]);
                    mma16816(acc[mf][nf], ahr, bl[nf]);
                    mma16816(acc[mf][nf], alr, bh[nf]);
                }
            }
        }
        __syncthreads();
    }

    const int qr = lane >> 2;
    const int qc = (lane & 3) * 2;
#pragma unroll
    for (int mf = 0; mf < 4; mf++) {
#pragma unroll
        for (int nf = 0; nf < 4; nf++) {
            int col = bn + wn + nf * 8 + qc;
            float b0 = bias[col], b1 = bias[col + 1];
            int r0 = bm + wm + mf * 16 + qr;
            float2 v0 = {acc[mf][nf][0] + b0, acc[mf][nf][1] + b1};
            float2 v1 = {acc[mf][nf][2] + b0, acc[mf][nf][3] + b1};
            *(float2*)&C[(size_t)r0 * DDIM + col] = v0;
            *(float2*)&C[(size_t)(r0 + 8) * DDIM + col] = v1;
        }
    }
}

// ---------------------------------------------------------------------------
// Q/K projection GEMM with fused bias + RoPE + bf16 hi/lo split epilogue.
// Warp tile 32x64 (4m x 2n warps) so each warp owns one full head (64 cols):
// the RoPE pair (col j, col j+32) sits in acc[.][nf] / acc[.][nf+4] of the
// SAME thread -> pure register rope.
// ---------------------------------------------------------------------------
__global__ void __launch_bounds__(256) mma_gemm_rope(
    const __nv_bfloat16* __restrict__ Ah, const __nv_bfloat16* __restrict__ Al,
    const __nv_bfloat16* __restrict__ Bh, const __nv_bfloat16* __restrict__ Bl,
    const float* __restrict__ bias,
    __nv_bfloat16* __restrict__ Ohi, __nv_bfloat16* __restrict__ Olo)
{
    extern __shared__ char gsm[];
    const uint32_t sb = smem_u32(gsm);

    const int tid = threadIdx.x;
    const int lane = tid & 31;
    const int wid = tid >> 5;
    const int wm = (wid & 3) * 32;    // 4 warps over m
    const int wn = (wid >> 2) * 64;   // 2 warps over n (one head each)
    const int bn = blockIdx.x * 128;
    const int bm = blockIdx.y * 128;

    float acc[2][8][4];
#pragma unroll
    for (int i = 0; i < 2; i++)
#pragma unroll
        for (int j = 0; j < 8; j++)
#pragma unroll
            for (int r = 0; r < 4; r++) acc[i][j][r] = 0.f;

    const int a_row = lane & 15;
    const int a_kof = (lane >> 4) << 3;
    const int b_n   = (lane & 7) + ((lane >> 4) << 3);
    const int b_kof = ((lane >> 3) & 1) << 3;

    const int ld_row = tid >> 2;
    const int ld_cg  = (tid & 3) * 8;

    G_LOAD(0, 0);
    CP_COMMIT();

    for (int kt = 0; kt < 32; kt++) {
        CP_WAIT0();
        __syncthreads();
        if (kt + 1 < 32) { G_LOAD(kt + 1, (kt + 1) & 1); CP_COMMIT(); }

        const uint32_t bufb = sb + (kt & 1) * GT_BUF;
#pragma unroll
        for (int ko = 0; ko < 32; ko += 16) {
            uint32_t bh[8][2], bl[8][2];
#pragma unroll
            for (int p = 0; p < 4; p++) {
                uint32_t t4[4];
                uint32_t boff = (wn + p * 16 + b_n) * GT_ROW + (ko + b_kof) * 2;
                ldm_x4(t4, bufb + 2 * GT_ARR + boff);
                bh[p * 2][0] = t4[0]; bh[p * 2][1] = t4[1];
                bh[p * 2 + 1][0] = t4[2]; bh[p * 2 + 1][1] = t4[3];
                ldm_x4(t4, bufb + 3 * GT_ARR + boff);
                bl[p * 2][0] = t4[0]; bl[p * 2][1] = t4[1];
                bl[p * 2 + 1][0] = t4[2]; bl[p * 2 + 1][1] = t4[3];
            }
#pragma unroll
            for (int mf = 0; mf < 2; mf++) {
                uint32_t ahr[4], alr[4];
                uint32_t aoff = (wm + mf * 16 + a_row) * GT_ROW + (ko + a_kof) * 2;
                ldm_x4(ahr, bufb + 0 * GT_ARR + aoff);
                ldm_x4(alr, bufb + 1 * GT_ARR + aoff);
#pragma unroll
                for (int nf = 0; nf < 8; nf++) {
                    mma16816(acc[mf][nf], ahr, bh[nf]);
                    mma16816(acc[mf][nf], ahr, bl[nf]);
                    mma16816(acc[mf][nf], alr, bh[nf]);
                }
            }
        }
        __syncthreads();
    }

    // ---- epilogue: bias + RoPE + bf16 split, direct store ----
    const int qr = lane >> 2;
    const int qc = (lane & 3) * 2;
    const int nb = bn + wn;  // head base column (multiple of 64)
#pragma unroll
    for (int mf = 0; mf < 2; mf++) {
#pragma unroll
        for (int rr = 0; rr < 2; rr++) {
            int m = bm + wm + mf * 16 + qr + rr * 8;
            int t = m & (TT - 1);
#pragma unroll
            for (int nf = 0; nf < 4; nf++) {
                int j = nf * 8 + qc;          // 0..30 (even)
                int jj = j >> 1;
                float c1 = g_cos[t * 32 + jj];
                float s1 = g_sin[t * 32 + jj];
                float c2 = g_cos[t * 32 + jj + 16];
                float s2 = g_sin[t * 32 + jj + 16];
                float a0 = acc[mf][nf][rr * 2 + 0] + bias[nb + j];
                float a1 = acc[mf][nf][rr * 2 + 1] + bias[nb + j + 1];
                float b0 = acc[mf][nf + 4][rr * 2 + 0] + bias[nb + j + 32];
                float b1 = acc[mf][nf + 4][rr * 2 + 1] + bias[nb + j + 33];
                float o0 = a0 * c1 - b0 * s1;
                float o1 = a1 * c1 - b1 * s1;
                float p0 = b0 * c2 + a0 * s2;
                float p1 = b1 * c2 + a1 * s2;
                size_t off0 = (size_t)m * DDIM + nb + j;
                size_t off1 = off0 + 32;
                uint32_t h0 = cvt_bf2(o0, o1), h1 = cvt_bf2(p0, p1);
                float2 u0 = unpack_bf2(h0), u1 = unpack_bf2(h1);
                uint32_t l0 = cvt_bf2(o0 - u0.x, o1 - u0.y);
                uint32_t l1 = cvt_bf2(p0 - u1.x, p1 - u1.y);
                *(uint32_t*)&Ohi[off0] = h0;
                *(uint32_t*)&Olo[off0] = l0;
                *(uint32_t*)&Ohi[off1] = h1;
                *(uint32_t*)&Olo[off1] = l1;
            }
        }
    }
}

// ---------------------------------------------------------------------------
// V transpose + split: g_v[b,t,h,dh] -> g_vt{hi,lo}[b,h,dh,T]
// ---------------------------------------------------------------------------
__global__ void vsplitT_kernel() {
    __shared__ float tile[32][33];
    int t0 = blockIdx.x * 32;
    int d0 = blockIdx.y * 32;
    int bh = blockIdx.z;
    int b = bh / HH, h = bh % HH;
    int tx = threadIdx.x, ty = threadIdx.y;
#pragma unroll
    for (int i = 0; i < 32; i += 8)
        tile[ty + i][tx] = g_v[((size_t)b * TT + t0 + ty + i) * DDIM + h * DHH + d0 + tx];
    __syncthreads();
#pragma unroll
    for (int i = 0; i < 32; i += 8) {
        float v = tile[tx][ty + i];
        size_t o = ((size_t)bh * DHH + d0 + ty + i) * TT + t0 + tx;
        __nv_bfloat16 hv = __float2bfloat16(v);
        g_vthi[o] = hv;
        g_vtlo[o] = __float2bfloat16(v - __bfloat162float(hv));
    }
}

// ---------------------------------------------------------------------------
// Flash attention with mma.sync, cp.async double-buffered K/V staging.
// Block: 128 q-rows x (b,h). 8 warps, each m16. k-tiles of 64.
// Launch-order reversed (heaviest q-tiles first) for tail balance.
// ---------------------------------------------------------------------------
#define AT_ROW 144
#define AT_ARR 9216
#define AT_BUF 36864
#define ATTN_SMEM (2 * AT_BUF)

__global__ void __launch_bounds__(256) attn_mma_kernel() {
    extern __shared__ char gsm[];
    const uint32_t sb = smem_u32(gsm);

    const int q0 = (gridDim.x - 1 - blockIdx.x) * 128;  // heavy blocks first
    const int h  = blockIdx.y;
    const int b  = blockIdx.z;
    const int tid = threadIdx.x;
    const int lane = tid & 31;
    const int wid = tid >> 5;
    const int wm = wid * 16;

    const size_t base_qk = (size_t)b * TT * DDIM + (size_t)h * DHH;
    const size_t base_vt = ((size_t)(b * HH + h)) * DHH * TT;

    const int a_row = lane & 15;
    const int a_kof = (lane >> 4) << 3;
    const int b_n   = (lane & 7) + ((lane >> 4) << 3);
    const int b_kof = ((lane >> 3) & 1) << 3;

    // ---- stage Q tile, load Q frags to registers ----
    for (int i = tid; i < 128 * 8; i += 256) {
        int r = i >> 3, c = (i & 7) * 8;
        size_t g = base_qk + (size_t)(q0 + r) * DDIM + c;
        *(uint4*)(gsm + r * AT_ROW + c * 2) = *(const uint4*)&g_qhi[g];
        *(uint4*)(gsm + 18432 + r * AT_ROW + c * 2) = *(const uint4*)&g_qlo[g];
    }
    __syncthreads();

    uint32_t qh[4][4], ql[4][4];
#pragma unroll
    for (int ko = 0; ko < 4; ko++) {
        uint32_t aoff = (wm + a_row) * AT_ROW + (ko * 16 + a_kof) * 2;
        ldm_x4(qh[ko], sb + aoff);
        ldm_x4(ql[ko], sb + 18432 + aoff);
    }
    __syncthreads();

    float m0 = -CUDART_INF_F, m1 = -CUDART_INF_F;
    float l0 = 0.f, l1 = 0.f;
    float o[8][4];
#pragma unroll
    for (int nf = 0; nf < 8; nf++)
#pragma unroll
        for (int r = 0; r < 4; r++) o[nf][r] = 0.f;

    const int nkt = q0 / 64 + 2;
    const float scale = 0.125f;

#define A_LOAD(kt, buf) do {                                                  \
        int k0_ = (kt) * 64;                                                  \
        _Pragma("unroll")                                                     \
        for (int i = tid; i < 512; i += 256) {                                \
            int r_ = i >> 3, c_ = (i & 7) * 8;                                \
            uint32_t so_ = sb + (buf) * AT_BUF + r_ * AT_ROW + c_ * 2;        \
            size_t gk_ = base_qk + (size_t)(k0_ + r_) * DDIM + c_;            \
            size_t gv_ = base_vt + (size_t)r_ * TT + k0_ + c_;                \
            cp16(so_ + 0 * AT_ARR, g_khi + gk_);                              \
            cp16(so_ + 1 * AT_ARR, g_klo + gk_);                              \
            cp16(so_ + 2 * AT_ARR, g_vthi + gv_);                             \
            cp16(so_ + 3 * AT_ARR, g_vtlo + gv_);                             \
        } } while (0)

    A_LOAD(0, 0);
    CP_COMMIT();

    for (int kt = 0; kt < nkt; kt++) {
        const int k0 = kt * 64;
        CP_WAIT0();
        __syncthreads();
        if (kt + 1 < nkt) { A_LOAD(kt + 1, (kt + 1) & 1); CP_COMMIT(); }

        const uint32_t bufb = sb + (kt & 1) * AT_BUF;

        if (k0 <= q0 + wm + 15) {
            float s[8][4];
#pragma unroll
            for (int nf = 0; nf < 8; nf++)
#pragma unroll
                for (int r = 0; r < 4; r++) s[nf][r] = 0.f;

#pragma unroll
            for (int ko = 0; ko < 4; ko++) {
#pragma unroll
                for (int p = 0; p < 4; p++) {
                    uint32_t th[4], tl[4];
                    uint32_t boff = (p * 16 + b_n) * AT_ROW + (ko * 16 + b_kof) * 2;
                    ldm_x4(th, bufb + 0 * AT_ARR + boff);
                    ldm_x4(tl, bufb + 1 * AT_ARR + boff);
                    mma16816(s[2 * p],     qh[ko], th);
                    mma16816(s[2 * p],     qh[ko], tl);
                    mma16816(s[2 * p],     ql[ko], th);
                    mma16816(s[2 * p + 1], qh[ko], th + 2);
                    mma16816(s[2 * p + 1], qh[ko], tl + 2);
                    mma16816(s[2 * p + 1], ql[ko], th + 2);
                }
            }

            const int qa = q0 + wm + (lane >> 2);
            const int qb = qa + 8;
            const bool need_mask = (k0 + 63 > q0 + wm);
#pragma unroll
            for (int nf = 0; nf < 8; nf++) {
                int cg = k0 + nf * 8 + (lane & 3) * 2;
                s[nf][0] *= scale; s[nf][1] *= scale;
                s[nf][2] *= scale; s[nf][3] *= scale;
                if (need_mask) {
                    if (cg > qa)     s[nf][0] = -10000.f;
                    if (cg + 1 > qa) s[nf][1] = -10000.f;
                    if (cg > qb)     s[nf][2] = -10000.f;
                    if (cg + 1 > qb) s[nf][3] = -10000.f;
                }
            }

            float rma = -CUDART_INF_F, rmb = -CUDART_INF_F;
#pragma unroll
            for (int nf = 0; nf < 8; nf++) {
                rma = fmaxf(rma, fmaxf(s[nf][0], s[nf][1]));
                rmb = fmaxf(rmb, fmaxf(s[nf][2], s[nf][3]));
            }
            rma = fmaxf(rma, __shfl_xor_sync(0xffffffffu, rma, 1));
            rma = fmaxf(rma, __shfl_xor_sync(0xffffffffu, rma, 2));
            rmb = fmaxf(rmb, __shfl_xor_sync(0xffffffffu, rmb, 1));
            rmb = fmaxf(rmb, __shfl_xor_sync(0xffffffffu, rmb, 2));
            float nma = fmaxf(m0, rma), nmb = fmaxf(m1, rmb);
            float alpha_a = __expf(m0 - nma), alpha_b = __expf(m1 - nmb);
            m0 = nma; m1 = nmb;

            float rsa = 0.f, rsb = 0.f;
#pragma unroll
            for (int nf = 0; nf < 8; nf++) {
                s[nf][0] = __expf(s[nf][0] - nma);
                s[nf][1] = __expf(s[nf][1] - nma);
                s[nf][2] = __expf(s[nf][2] - nmb);
                s[nf][3] = __expf(s[nf][3] - nmb);
                rsa += s[nf][0] + s[nf][1];
                rsb += s[nf][2] + s[nf][3];
            }
            rsa += __shfl_xor_sync(0xffffffffu, rsa, 1);
            rsa += __shfl_xor_sync(0xffffffffu, rsa, 2);
            rsb += __shfl_xor_sync(0xffffffffu, rsb, 1);
            rsb += __shfl_xor_sync(0xffffffffu, rsb, 2);
            l0 = l0 * alpha_a + rsa;
            l1 = l1 * alpha_b + rsb;

#pragma unroll
            for (int nf = 0; nf < 8; nf++) {
                o[nf][0] *= alpha_a; o[nf][1] *= alpha_a;
                o[nf][2] *= alpha_b; o[nf][3] *= alpha_b;
            }

            uint32_t ph[4][4], pl[4][4];
#pragma unroll
            for (int kb = 0; kb < 4; kb++) {
                float* f0 = s[2 * kb];
                float* f1 = s[2 * kb + 1];
                ph[kb][0] = cvt_bf2(f0[0], f0[1]);
                ph[kb][1] = cvt_bf2(f0[2], f0[3]);
                ph[kb][2] = cvt_bf2(f1[0], f1[1]);
                ph[kb][3] = cvt_bf2(f1[2], f1[3]);
                float2 u;
                u = unpack_bf2(ph[kb][0]); pl[kb][0] = cvt_bf2(f0[0] - u.x, f0[1] - u.y);
                u = unpack_bf2(ph[kb][1]); pl[kb][1] = cvt_bf2(f0[2] - u.x, f0[3] - u.y);
                u = unpack_bf2(ph[kb][2]); pl[kb][2] = cvt_bf2(f1[0] - u.x, f1[1] - u.y);
                u = unpack_bf2(ph[kb][3]); pl[kb][3] = cvt_bf2(f1[2] - u.x, f1[3] - u.y);
            }

#pragma unroll
            for (int kb = 0; kb < 4; kb++) {
#pragma unroll
                for (int p = 0; p < 4; p++) {
                    uint32_t th[4], tl[4];
                    uint32_t boff = (p * 16 + b_n) * AT_ROW + (kb * 16 + b_kof) * 2;
                    ldm_x4(th, bufb + 2 * AT_ARR + boff);
                    ldm_x4(tl, bufb + 3 * AT_ARR + boff);
                    mma16816(o[2 * p],     ph[kb], th);
                    mma16816(o[2 * p],     ph[kb], tl);
                    mma16816(o[2 * p],     pl[kb], th);
                    mma16816(o[2 * p + 1], ph[kb], th + 2);
                    mma16816(o[2 * p + 1], ph[kb], tl + 2);
                    mma16816(o[2 * p + 1], pl[kb], th + 2);
                }
            }
        }
        __syncthreads();
    }
#undef A_LOAD

    // ---- epilogue: normalize + write bf16 hi/lo directly ----
    float inv_a = 1.0f / l0, inv_b = 1.0f / l1;
    int ra = q0 + wm + (lane >> 2);
    int cq = (lane & 3) * 2;
#pragma unroll
    for (int nf = 0; nf < 8; nf++) {
        int col = h * DHH + nf * 8 + cq;
        float v0 = o[nf][0] * inv_a, v1 = o[nf][1] * inv_a;
        float v2 = o[nf][2] * inv_b, v3 = o[nf][3] * inv_b;
        size_t o0 = ((size_t)b * TT + ra) * DDIM + col;
        size_t o1 = ((size_t)b * TT + ra + 8) * DDIM + col;
        uint32_t h0 = cvt_bf2(v0, v1), h1 = cvt_bf2(v2, v3);
        float2 u0 = unpack_bf2(h0), u1 = unpack_bf2(h1);
        uint32_t l0w = cvt_bf2(v0 - u0.x, v1 - u0.y);
        uint32_t l1w = cvt_bf2(v2 - u1.x, v3 - u1.y);
        *(uint32_t*)&g_ahi[o0] = h0;
        *(uint32_t*)&g_alo[o0] = l0w;
        *(uint32_t*)&g_ahi[o1] = h1;
        *(uint32_t*)&g_alo[o1] = l1w;
    }
}

// ---------------------------------------------------------------------------
// Launch
// ---------------------------------------------------------------------------
extern "C" void kernel_launch(void* const* d_in, const int* in_sizes, int n_in,
                              void* d_out, int out_size)
{
    const float* x  = (const float*)d_in[0];
    const float* wq = (const float*)d_in[2];
    const float* bq = (const float*)d_in[3];
    const float* wk = (const float*)d_in[4];
    const float* bk = (const float*)d_in[5];
    const float* wv = (const float*)d_in[6];
    const float* bv = (const float*)d_in[7];
    const float* wo = (const float*)d_in[8];
    const float* bo = (const float*)d_in[9];
    float* out = (float*)d_out;

    float *vp;
    __nv_bfloat16 *ahi, *alo, *whi, *wlo, *qhi, *qlo, *khi, *klo;
    cudaGetSymbolAddress((void**)&vp, g_v);
    cudaGetSymbolAddress((void**)&ahi, g_ahi);
    cudaGetSymbolAddress((void**)&alo, g_alo);
    cudaGetSymbolAddress((void**)&whi, g_whi);
    cudaGetSymbolAddress((void**)&wlo, g_wlo);
    cudaGetSymbolAddress((void**)&qhi, g_qhi);
    cudaGetSymbolAddress((void**)&qlo, g_qlo);
    cudaGetSymbolAddress((void**)&khi, g_khi);
    cudaGetSymbolAddress((void**)&klo, g_klo);

    const size_t WSZ = (size_t)DDIM * DDIM;

    sincos_kernel<<<(TT * 32 + 255) / 256, 256>>>();

    const int n4 = MM * DDIM / 4;
    split_kernel<<<(n4 + 255) / 256, 256>>>(x, ahi, alo, n4);
    dim3 tgrid(32, 32), tblk(32, 8);
    splitT_kernel<<<tgrid, tblk>>>(wq, whi + 0 * WSZ, wlo + 0 * WSZ);
    splitT_kernel<<<tgrid, tblk>>>(wk, whi + 1 * WSZ, wlo + 1 * WSZ);
    splitT_kernel<<<tgrid, tblk>>>(wv, whi + 2 * WSZ, wlo + 2 * WSZ);
    splitT_kernel<<<tgrid, tblk>>>(wo, whi + 3 * WSZ, wlo + 3 * WSZ);

    cudaFuncSetAttribute(mma_gemm, cudaFuncAttributeMaxDynamicSharedMemorySize,
                         GEMM_SMEM);
    cudaFuncSetAttribute(mma_gemm_rope,
                         cudaFuncAttributeMaxDynamicSharedMemorySize, GEMM_SMEM);
    dim3 ggrid(DDIM / 128, MM / 128);
    // Q,K projections with fused rope+split epilogue
    mma_gemm_rope<<<ggrid, 256, GEMM_SMEM>>>(ahi, alo, whi + 0 * WSZ, wlo + 0 * WSZ,
                                             bq, qhi, qlo);
    mma_gemm_rope<<<ggrid, 256, GEMM_SMEM>>>(ahi, alo, whi + 1 * WSZ, wlo + 1 * WSZ,
                                             bk, khi, klo);
    // V projection (fp32 out, then transpose+split)
    mma_gemm<<<ggrid, 256, GEMM_SMEM>>>(ahi, alo, whi + 2 * WSZ, wlo + 2 * WSZ, bv, vp);
    vsplitT_kernel<<<dim3(TT / 32, DHH / 32, BB * HH), dim3(32, 8)>>>();

    // tensor-core flash attention (writes ahi/alo directly)
    cudaFuncSetAttribute(attn_mma_kernel,
                         cudaFuncAttributeMaxDynamicSharedMemorySize, ATTN_SMEM);
    attn_mma_kernel<<<dim3(TT / 128, HH, BB), 256, ATTN_SMEM>>>();

    // out-projection
    mma_gemm<<<ggrid, 256, GEMM_SMEM>>>(ahi, alo, whi + 3 * WSZ, wlo + 3 * WSZ, bo, out);
}

// round 10
// speedup vs baseline: 1.0169x; 1.0169x over previous
#include <cuda_runtime.h>
#include <cuda_bf16.h>
#include <math.h>
#include <math_constants.h>
#include <cstdint>

// Problem constants
#define BB  2
#define TT  2048
#define DDIM 1024
#define HH  16
#define DHH 64
#define MM  (BB*TT)

// ---------------------------------------------------------------------------
// Scratch (device globals)
// ---------------------------------------------------------------------------
__device__ float g_sin[TT * 32];
__device__ float g_cos[TT * 32];

__device__ __nv_bfloat16 g_ahi[(size_t)MM * DDIM];
__device__ __nv_bfloat16 g_alo[(size_t)MM * DDIM];
__device__ __nv_bfloat16 g_whi[(size_t)4 * DDIM * DDIM];
__device__ __nv_bfloat16 g_wlo[(size_t)4 * DDIM * DDIM];

// attention bf16 operands
__device__ __nv_bfloat16 g_qhi[(size_t)MM * DDIM];
__device__ __nv_bfloat16 g_qlo[(size_t)MM * DDIM];
__device__ __nv_bfloat16 g_khi[(size_t)MM * DDIM];
__device__ __nv_bfloat16 g_klo[(size_t)MM * DDIM];
__device__ __nv_bfloat16 g_vthi[(size_t)MM * DDIM];  // [b,h,dh,T]
__device__ __nv_bfloat16 g_vtlo[(size_t)MM * DDIM];

// ---------------------------------------------------------------------------
// Warp tensor helpers (baseline PTX: ldmatrix + mma.sync + cp.async)
// ---------------------------------------------------------------------------
__device__ __forceinline__ uint32_t smem_u32(const void* p) {
    uint32_t a;
    asm("{ .reg .u64 t; cvta.to.shared.u64 t, %1; cvt.u32.u64 %0, t; }"
        : "=r"(a) : "l"(p));
    return a;
}

__device__ __forceinline__ void ldm_x4(uint32_t* r, uint32_t addr) {
    asm volatile("ldmatrix.sync.aligned.m8n8.x4.shared.b16 {%0,%1,%2,%3}, [%4];"
                 : "=r"(r[0]), "=r"(r[1]), "=r"(r[2]), "=r"(r[3]) : "r"(addr));
}

__device__ __forceinline__ void mma16816(float* c, const uint32_t* a,
                                         const uint32_t* b) {
    asm volatile(
        "mma.sync.aligned.m16n8k16.row.col.f32.bf16.bf16.f32 "
        "{%0,%1,%2,%3}, {%4,%5,%6,%7}, {%8,%9}, {%0,%1,%2,%3};"
        : "+f"(c[0]), "+f"(c[1]), "+f"(c[2]), "+f"(c[3])
        : "r"(a[0]), "r"(a[1]), "r"(a[2]), "r"(a[3]), "r"(b[0]), "r"(b[1]));
}

__device__ __forceinline__ void cp16(uint32_t dst, const void* src) {
    asm volatile("cp.async.cg.shared.global [%0], [%1], 16;"
                 :: "r"(dst), "l"(src));
}
#define CP_COMMIT() asm volatile("cp.async.commit_group;" ::: "memory")
#define CP_WAIT0()  asm volatile("cp.async.wait_group 0;" ::: "memory")

__device__ __forceinline__ uint32_t cvt_bf2(float lo, float hi) {
    uint32_t r;
    asm("cvt.rn.bf16x2.f32 %0, %1, %2;" : "=r"(r) : "f"(hi), "f"(lo));
    return r;
}
__device__ __forceinline__ float2 unpack_bf2(uint32_t v) {
    __nv_bfloat162 b = *reinterpret_cast<__nv_bfloat162*>(&v);
    return __bfloat1622float2(b);
}

// ---------------------------------------------------------------------------
// RoPE sin/cos table
// ---------------------------------------------------------------------------
__global__ void sincos_kernel() {
    int idx = blockIdx.x * blockDim.x + threadIdx.x;
    if (idx >= TT * 32) return;
    int t  = idx >> 5;
    int jj = idx & 31;
    double ang = (double)t * pow(10000.0, -2.0 * (double)jj / 64.0);
    g_sin[idx] = (float)sin(ang);
    g_cos[idx] = (float)cos(ang);
}

// ---------------------------------------------------------------------------
// fp32 -> bf16 hi/lo split (vectorized)
// ---------------------------------------------------------------------------
__global__ void split_kernel(const float* __restrict__ src,
                             __nv_bfloat16* __restrict__ hi,
                             __nv_bfloat16* __restrict__ lo, int n4) {
    int i = blockIdx.x * blockDim.x + threadIdx.x;
    if (i >= n4) return;
    float4 v = ((const float4*)src)[i];
    __nv_bfloat16 h0 = __float2bfloat16(v.x), h1 = __float2bfloat16(v.y);
    __nv_bfloat16 h2 = __float2bfloat16(v.z), h3 = __float2bfloat16(v.w);
    uint2 hh, ll;
    hh.x = cvt_bf2(v.x, v.y); hh.y = cvt_bf2(v.z, v.w);
    ll.x = cvt_bf2(v.x - __bfloat162float(h0), v.y - __bfloat162float(h1));
    ll.y = cvt_bf2(v.z - __bfloat162float(h2), v.w - __bfloat162float(h3));
    ((uint2*)hi)[i] = hh;
    ((uint2*)lo)[i] = ll;
}

// fp32 W[K,N] -> bf16 hi/lo transposed [N,K]
__global__ void splitT_kernel(const float* __restrict__ w,
                              __nv_bfloat16* __restrict__ hi,
                              __nv_bfloat16* __restrict__ lo) {
    __shared__ float tile[32][33];
    int bx = blockIdx.x * 32;
    int by = blockIdx.y * 32;
    int tx = threadIdx.x, ty = threadIdx.y;
#pragma unroll
    for (int i = 0; i < 32; i += 8)
        tile[ty + i][tx] = w[(size_t)(by + ty + i) * DDIM + bx + tx];
    __syncthreads();
#pragma unroll
    for (int i = 0; i < 32; i += 8) {
        float v = tile[tx][ty + i];
        size_t o = (size_t)(bx + ty + i) * DDIM + by + tx;
        __nv_bfloat16 h = __float2bfloat16(v);
        hi[o] = h;
        lo[o] = __float2bfloat16(v - __bfloat162float(h));
    }
}

// ---------------------------------------------------------------------------
// Shared GEMM mainloop (proven round-7 shape: 8 warps, warp tile 64x32)
// ---------------------------------------------------------------------------
#define GT_ROW 80        // bytes per smem row (40 bf16)
#define GT_ARR 10240     // bytes per tile array (128*80)
#define GT_BUF 40960     // bytes per stage (4 arrays)
#define GEMM_SMEM (2 * GT_BUF)

#define G_LOAD(kt, buf) do {                                                  \
        int k0_ = (kt) * 32;                                                  \
        _Pragma("unroll")                                                     \
        for (int half = 0; half < 2; half++) {                                \
            int row_ = half * 64 + ld_row;                                    \
            size_t ga_ = (size_t)(bm + row_) * DDIM + k0_ + ld_cg;            \
            size_t gb_ = (size_t)(bn + row_) * DDIM + k0_ + ld_cg;            \
            uint32_t so_ = sb + (buf) * GT_BUF + row_ * GT_ROW + ld_cg * 2;   \
            cp16(so_ + 0 * GT_ARR, Ah + ga_);                                 \
            cp16(so_ + 1 * GT_ARR, Al + ga_);                                 \
            cp16(so_ + 2 * GT_ARR, Bh + gb_);                                 \
            cp16(so_ + 3 * GT_ARR, Bl + gb_);                                 \
        } } while (0)

// The mainloop body (identical in all GEMM variants)
#define G_MAINLOOP()                                                          \
    G_LOAD(0, 0);                                                             \
    CP_COMMIT();                                                              \
    for (int kt = 0; kt < 32; kt++) {                                         \
        CP_WAIT0();                                                           \
        __syncthreads();                                                      \
        if (kt + 1 < 32) { G_LOAD(kt + 1, (kt + 1) & 1); CP_COMMIT(); }       \
        const uint32_t bufb = sb + (kt & 1) * GT_BUF;                         \
        _Pragma("unroll")                                                     \
        for (int ko = 0; ko < 32; ko += 16) {                                 \
            uint32_t bh[4][2], bl[4][2];                                      \
            _Pragma("unroll")                                                 \
            for (int p = 0; p < 2; p++) {                                     \
                uint32_t t4[4];                                               \
                uint32_t boff = (wn + p * 16 + b_n) * GT_ROW + (ko + b_kof) * 2; \
                ldm_x4(t4, bufb + 2 * GT_ARR + boff);                         \
                bh[p * 2][0] = t4[0]; bh[p * 2][1] = t4[1];                   \
                bh[p * 2 + 1][0] = t4[2]; bh[p * 2 + 1][1] = t4[3];           \
                ldm_x4(t4, bufb + 3 * GT_ARR + boff);                         \
                bl[p * 2][0] = t4[0]; bl[p * 2][1] = t4[1];                   \
                bl[p * 2 + 1][0] = t4[2]; bl[p * 2 + 1][1] = t4[3];           \
            }                                                                 \
            _Pragma("unroll")                                                 \
            for (int mf = 0; mf < 4; mf++) {                                  \
                uint32_t ahr[4], alr[4];                                      \
                uint32_t aoff = (wm + mf * 16 + a_row) * GT_ROW + (ko + a_kof) * 2; \
                ldm_x4(ahr, bufb + 0 * GT_ARR + aoff);                        \
                ldm_x4(alr, bufb + 1 * GT_ARR + aoff);                        \
                _Pragma("unroll")                                             \
                for (int nf = 0; nf < 4; nf++) {                              \
                    mma16816(acc[mf][nf], ahr, bh[nf]);                       \
                    mma16816(acc[mf][nf], ahr, bl[nf]);                       \
                    mma16816(acc[mf][nf], alr, bh[nf]);                       \
                }                                                             \
            }                                                                 \
        }                                                                     \
        __syncthreads();                                                      \
    }

#define G_PROLOG()                                                            \
    extern __shared__ char gsm[];                                             \
    const uint32_t sb = smem_u32(gsm);                                        \
    const int tid = threadIdx.x;                                              \
    const int lane = tid & 31;                                                \
    const int wid = tid >> 5;                                                 \
    const int wm = (wid & 1) * 64;                                            \
    const int wn = (wid >> 1) * 32;                                           \
    const int bn = blockIdx.x * 128;                                          \
    const int bm = blockIdx.y * 128;                                          \
    float acc[4][4][4];                                                       \
    _Pragma("unroll")                                                         \
    for (int i = 0; i < 4; i++)                                               \
        _Pragma("unroll")                                                     \
        for (int j = 0; j < 4; j++)                                           \
            _Pragma("unroll")                                                 \
            for (int r = 0; r < 4; r++) acc[i][j][r] = 0.f;                   \
    const int a_row = lane & 15;                                              \
    const int a_kof = (lane >> 4) << 3;                                       \
    const int b_n   = (lane & 7) + ((lane >> 4) << 3);                        \
    const int b_kof = ((lane >> 3) & 1) << 3;                                 \
    const int ld_row = tid >> 2;                                              \
    const int ld_cg  = (tid & 3) * 8;

// Store acc + bias into fp32 staging smem [128][129]
#define G_STAGE_SMEM()                                                        \
    float* Ssm = (float*)gsm;                                                 \
    {                                                                         \
        const int qr = lane >> 2;                                             \
        const int qc = (lane & 3) * 2;                                        \
        _Pragma("unroll")                                                     \
        for (int mf = 0; mf < 4; mf++) {                                      \
            _Pragma("unroll")                                                 \
            for (int nf = 0; nf < 4; nf++) {                                  \
                int row = wm + mf * 16 + qr;                                  \
                int col = wn + nf * 8 + qc;                                   \
                float b0 = bias[bn + col], b1 = bias[bn + col + 1];           \
                Ssm[row * 129 + col]     = acc[mf][nf][0] + b0;               \
                Ssm[row * 129 + col + 1] = acc[mf][nf][1] + b1;               \
                Ssm[(row + 8) * 129 + col]     = acc[mf][nf][2] + b0;         \
                Ssm[(row + 8) * 129 + col + 1] = acc[mf][nf][3] + b1;         \
            }                                                                 \
        }                                                                     \
    }                                                                         \
    __syncthreads();

// ---------------------------------------------------------------------------
// Plain GEMM: fp32 output + bias (used for out-projection)
// ---------------------------------------------------------------------------
__global__ void __launch_bounds__(256) mma_gemm(
    const __nv_bfloat16* __restrict__ Ah, const __nv_bfloat16* __restrict__ Al,
    const __nv_bfloat16* __restrict__ Bh, const __nv_bfloat16* __restrict__ Bl,
    const float* __restrict__ bias, float* __restrict__ C)
{
    G_PROLOG();
    G_MAINLOOP();

    const int qr = lane >> 2;
    const int qc = (lane & 3) * 2;
#pragma unroll
    for (int mf = 0; mf < 4; mf++) {
#pragma unroll
        for (int nf = 0; nf < 4; nf++) {
            int col = bn + wn + nf * 8 + qc;
            float b0 = bias[col], b1 = bias[col + 1];
            int r0 = bm + wm + mf * 16 + qr;
            float2 v0 = {acc[mf][nf][0] + b0, acc[mf][nf][1] + b1};
            float2 v1 = {acc[mf][nf][2] + b0, acc[mf][nf][3] + b1};
            *(float2*)&C[(size_t)r0 * DDIM + col] = v0;
            *(float2*)&C[(size_t)(r0 + 8) * DDIM + col] = v1;
        }
    }
}

// ---------------------------------------------------------------------------
// Q/K GEMM: smem-staged epilogue with fused bias + RoPE + bf16 split.
// ---------------------------------------------------------------------------
__global__ void __launch_bounds__(256) mma_gemm_rope(
    const __nv_bfloat16* __restrict__ Ah, const __nv_bfloat16* __restrict__ Al,
    const __nv_bfloat16* __restrict__ Bh, const __nv_bfloat16* __restrict__ Bl,
    const float* __restrict__ bias,
    __nv_bfloat16* __restrict__ Ohi, __nv_bfloat16* __restrict__ Olo)
{
    G_PROLOG();
    G_MAINLOOP();
    G_STAGE_SMEM();

    // 128 rows x 2 heads x 32 pairs = 8192 rope pairs
    for (int p = tid; p < 8192; p += 256) {
        int j  = p & 31;
        int hh = (p >> 5) & 1;
        int m  = p >> 6;
        int gm = bm + m;
        int t  = gm & (TT - 1);
        int cb = hh * 64;
        float a  = Ssm[m * 129 + cb + j];
        float bv = Ssm[m * 129 + cb + j + 32];
        int jj = j >> 1;
        float c1 = g_cos[t * 32 + jj],      s1 = g_sin[t * 32 + jj];
        float c2 = g_cos[t * 32 + jj + 16], s2 = g_sin[t * 32 + jj + 16];
        float o0 = a * c1 - bv * s1;
        float o1 = bv * c2 + a * s2;
        size_t off = (size_t)gm * DDIM + bn + cb + j;
        __nv_bfloat16 h0 = __float2bfloat16(o0);
        __nv_bfloat16 h1 = __float2bfloat16(o1);
        Ohi[off]      = h0;
        Olo[off]      = __float2bfloat16(o0 - __bfloat162float(h0));
        Ohi[off + 32] = h1;
        Olo[off + 32] = __float2bfloat16(o1 - __bfloat162float(h1));
    }
}

// ---------------------------------------------------------------------------
// V GEMM: smem-staged epilogue with fused bias + transpose + bf16 split.
// Output to g_vt{hi,lo}[b,h,dh,T] with T-coalesced writes.
// FIX(r9): T-coordinate is bm within the batch (bm & (TT-1)), not global bm.
// ---------------------------------------------------------------------------
__global__ void __launch_bounds__(256) mma_gemm_vt(
    const __nv_bfloat16* __restrict__ Ah, const __nv_bfloat16* __restrict__ Al,
    const __nv_bfloat16* __restrict__ Bh, const __nv_bfloat16* __restrict__ Bl,
    const float* __restrict__ bias)
{
    G_PROLOG();
    G_MAINLOOP();
    G_STAGE_SMEM();

    const int bq_ = bm >> 11;           // batch index (TT=2048 rows per batch)
    const int tm  = bm & (TT - 1);      // tile's T-offset within the batch
#pragma unroll
    for (int ci = 0; ci < 16; ci++) {
        int c = wid + ci * 8;              // this warp's column
        int gcol = bn + c;
        int hh = gcol >> 6, d = gcol & 63;
        size_t obase = ((size_t)(bq_ * HH + hh) * DHH + d) * TT + tm;
#pragma unroll
        for (int rj = 0; rj < 4; rj++) {
            int row = lane + rj * 32;
            float v = Ssm[row * 129 + c];
            __nv_bfloat16 hv = __float2bfloat16(v);
            g_vthi[obase + row] = hv;
            g_vtlo[obase + row] = __float2bfloat16(v - __bfloat162float(hv));
        }
    }
}

// ---------------------------------------------------------------------------
// Flash attention with mma.sync, cp.async double-buffered K/V staging.
// Block: 128 q-rows x (b,h). 8 warps, each m16. k-tiles of 64.
// ---------------------------------------------------------------------------
#define AT_ROW 144
#define AT_ARR 9216
#define AT_BUF 36864
#define ATTN_SMEM (2 * AT_BUF)

__global__ void __launch_bounds__(256) attn_mma_kernel() {
    extern __shared__ char gsm[];
    const uint32_t sb = smem_u32(gsm);

    const int q0 = blockIdx.x * 128;
    const int h  = blockIdx.y;
    const int b  = blockIdx.z;
    const int tid = threadIdx.x;
    const int lane = tid & 31;
    const int wid = tid >> 5;
    const int wm = wid * 16;

    const size_t base_qk = (size_t)b * TT * DDIM + (size_t)h * DHH;
    const size_t base_vt = ((size_t)(b * HH + h)) * DHH * TT;

    const int a_row = lane & 15;
    const int a_kof = (lane >> 4) << 3;
    const int b_n   = (lane & 7) + ((lane >> 4) << 3);
    const int b_kof = ((lane >> 3) & 1) << 3;

    // ---- stage Q tile, load Q frags to registers ----
    for (int i = tid; i < 128 * 8; i += 256) {
        int r = i >> 3, c = (i & 7) * 8;
        size_t g = base_qk + (size_t)(q0 + r) * DDIM + c;
        *(uint4*)(gsm + r * AT_ROW + c * 2) = *(const uint4*)&g_qhi[g];
        *(uint4*)(gsm + 18432 + r * AT_ROW + c * 2) = *(const uint4*)&g_qlo[g];
    }
    __syncthreads();

    uint32_t qh[4][4], ql[4][4];
#pragma unroll
    for (int ko = 0; ko < 4; ko++) {
        uint32_t aoff = (wm + a_row) * AT_ROW + (ko * 16 + a_kof) * 2;
        ldm_x4(qh[ko], sb + aoff);
        ldm_x4(ql[ko], sb + 18432 + aoff);
    }
    __syncthreads();

    float m0 = -CUDART_INF_F, m1 = -CUDART_INF_F;
    float l0 = 0.f, l1 = 0.f;
    float o[8][4];
#pragma unroll
    for (int nf = 0; nf < 8; nf++)
#pragma unroll
        for (int r = 0; r < 4; r++) o[nf][r] = 0.f;

    const int nkt = q0 / 64 + 2;
    const float scale = 0.125f;

#define A_LOAD(kt, buf) do {                                                  \
        int k0_ = (kt) * 64;                                                  \
        _Pragma("unroll")                                                     \
        for (int i = tid; i < 512; i += 256) {                                \
            int r_ = i >> 3, c_ = (i & 7) * 8;                                \
            uint32_t so_ = sb + (buf) * AT_BUF + r_ * AT_ROW + c_ * 2;        \
            size_t gk_ = base_qk + (size_t)(k0_ + r_) * DDIM + c_;            \
            size_t gv_ = base_vt + (size_t)r_ * TT + k0_ + c_;                \
            cp16(so_ + 0 * AT_ARR, g_khi + gk_);                              \
            cp16(so_ + 1 * AT_ARR, g_klo + gk_);                              \
            cp16(so_ + 2 * AT_ARR, g_vthi + gv_);                             \
            cp16(so_ + 3 * AT_ARR, g_vtlo + gv_);                             \
        } } while (0)

    A_LOAD(0, 0);
    CP_COMMIT();

    for (int kt = 0; kt < nkt; kt++) {
        const int k0 = kt * 64;
        CP_WAIT0();
        __syncthreads();
        if (kt + 1 < nkt) { A_LOAD(kt + 1, (kt + 1) & 1); CP_COMMIT(); }

        const uint32_t bufb = sb + (kt & 1) * AT_BUF;

        if (k0 <= q0 + wm + 15) {
            float s[8][4];
#pragma unroll
            for (int nf = 0; nf < 8; nf++)
#pragma unroll
                for (int r = 0; r < 4; r++) s[nf][r] = 0.f;

#pragma unroll
            for (int ko = 0; ko < 4; ko++) {
#pragma unroll
                for (int p = 0; p < 4; p++) {
                    uint32_t th[4], tl[4];
                    uint32_t boff = (p * 16 + b_n) * AT_ROW + (ko * 16 + b_kof) * 2;
                    ldm_x4(th, bufb + 0 * AT_ARR + boff);
                    ldm_x4(tl, bufb + 1 * AT_ARR + boff);
                    mma16816(s[2 * p],     qh[ko], th);
                    mma16816(s[2 * p],     qh[ko], tl);
                    mma16816(s[2 * p],     ql[ko], th);
                    mma16816(s[2 * p + 1], qh[ko], th + 2);
                    mma16816(s[2 * p + 1], qh[ko], tl + 2);
                    mma16816(s[2 * p + 1], ql[ko], th + 2);
                }
            }

            const int qa = q0 + wm + (lane >> 2);
            const int qb = qa + 8;
            const bool need_mask = (k0 + 63 > q0 + wm);
#pragma unroll
            for (int nf = 0; nf < 8; nf++) {
                int cg = k0 + nf * 8 + (lane & 3) * 2;
                s[nf][0] *= scale; s[nf][1] *= scale;
                s[nf][2] *= scale; s[nf][3] *= scale;
                if (need_mask) {
                    if (cg > qa)     s[nf][0] = -10000.f;
                    if (cg + 1 > qa) s[nf][1] = -10000.f;
                    if (cg > qb)     s[nf][2] = -10000.f;
                    if (cg + 1 > qb) s[nf][3] = -10000.f;
                }
            }

            float rma = -CUDART_INF_F, rmb = -CUDART_INF_F;
#pragma unroll
            for (int nf = 0; nf < 8; nf++) {
                rma = fmaxf(rma, fmaxf(s[nf][0], s[nf][1]));
                rmb = fmaxf(rmb, fmaxf(s[nf][2], s[nf][3]));
            }
            rma = fmaxf(rma, __shfl_xor_sync(0xffffffffu, rma, 1));
            rma = fmaxf(rma, __shfl_xor_sync(0xffffffffu, rma, 2));
            rmb = fmaxf(rmb, __shfl_xor_sync(0xffffffffu, rmb, 1));
            rmb = fmaxf(rmb, __shfl_xor_sync(0xffffffffu, rmb, 2));
            float nma = fmaxf(m0, rma), nmb = fmaxf(m1, rmb);
            float alpha_a = __expf(m0 - nma), alpha_b = __expf(m1 - nmb);
            m0 = nma; m1 = nmb;

            float rsa = 0.f, rsb = 0.f;
#pragma unroll
            for (int nf = 0; nf < 8; nf++) {
                s[nf][0] = __expf(s[nf][0] - nma);
                s[nf][1] = __expf(s[nf][1] - nma);
                s[nf][2] = __expf(s[nf][2] - nmb);
                s[nf][3] = __expf(s[nf][3] - nmb);
                rsa += s[nf][0] + s[nf][1];
                rsb += s[nf][2] + s[nf][3];
            }
            rsa += __shfl_xor_sync(0xffffffffu, rsa, 1);
            rsa += __shfl_xor_sync(0xffffffffu, rsa, 2);
            rsb += __shfl_xor_sync(0xffffffffu, rsb, 1);
            rsb += __shfl_xor_sync(0xffffffffu, rsb, 2);
            l0 = l0 * alpha_a + rsa;
            l1 = l1 * alpha_b + rsb;

#pragma unroll
            for (int nf = 0; nf < 8; nf++) {
                o[nf][0] *= alpha_a; o[nf][1] *= alpha_a;
                o[nf][2] *= alpha_b; o[nf][3] *= alpha_b;
            }

            uint32_t ph[4][4], pl[4][4];
#pragma unroll
            for (int kb = 0; kb < 4; kb++) {
                float* f0 = s[2 * kb];
                float* f1 = s[2 * kb + 1];
                ph[kb][0] = cvt_bf2(f0[0], f0[1]);
                ph[kb][1] = cvt_bf2(f0[2], f0[3]);
                ph[kb][2] = cvt_bf2(f1[0], f1[1]);
                ph[kb][3] = cvt_bf2(f1[2], f1[3]);
                float2 u;
                u = unpack_bf2(ph[kb][0]); pl[kb][0] = cvt_bf2(f0[0] - u.x, f0[1] - u.y);
                u = unpack_bf2(ph[kb][1]); pl[kb][1] = cvt_bf2(f0[2] - u.x, f0[3] - u.y);
                u = unpack_bf2(ph[kb][2]); pl[kb][2] = cvt_bf2(f1[0] - u.x, f1[1] - u.y);
                u = unpack_bf2(ph[kb][3]); pl[kb][3] = cvt_bf2(f1[2] - u.x, f1[3] - u.y);
            }

#pragma unroll
            for (int kb = 0; kb < 4; kb++) {
#pragma unroll
                for (int p = 0; p < 4; p++) {
                    uint32_t th[4], tl[4];
                    uint32_t boff = (p * 16 + b_n) * AT_ROW + (kb * 16 + b_kof) * 2;
                    ldm_x4(th, bufb + 2 * AT_ARR + boff);
                    ldm_x4(tl, bufb + 3 * AT_ARR + boff);
                    mma16816(o[2 * p],     ph[kb], th);
                    mma16816(o[2 * p],     ph[kb], tl);
                    mma16816(o[2 * p],     pl[kb], th);
                    mma16816(o[2 * p + 1], ph[kb], th + 2);
                    mma16816(o[2 * p + 1], ph[kb], tl + 2);
                    mma16816(o[2 * p + 1], pl[kb], th + 2);
                }
            }
        }
        __syncthreads();
    }
#undef A_LOAD

    // ---- epilogue: normalize + write bf16 hi/lo directly ----
    float inv_a = 1.0f / l0, inv_b = 1.0f / l1;
    int ra = q0 + wm + (lane >> 2);
    int cq = (lane & 3) * 2;
#pragma unroll
    for (int nf = 0; nf < 8; nf++) {
        int col = h * DHH + nf * 8 + cq;
        float v0 = o[nf][0] * inv_a, v1 = o[nf][1] * inv_a;
        float v2 = o[nf][2] * inv_b, v3 = o[nf][3] * inv_b;
        size_t o0 = ((size_t)b * TT + ra) * DDIM + col;
        size_t o1 = ((size_t)b * TT + ra + 8) * DDIM + col;
        uint32_t h0 = cvt_bf2(v0, v1), h1 = cvt_bf2(v2, v3);
        float2 u0 = unpack_bf2(h0), u1 = unpack_bf2(h1);
        uint32_t l0w = cvt_bf2(v0 - u0.x, v1 - u0.y);
        uint32_t l1w = cvt_bf2(v2 - u1.x, v3 - u1.y);
        *(uint32_t*)&g_ahi[o0] = h0;
        *(uint32_t*)&g_alo[o0] = l0w;
        *(uint32_t*)&g_ahi[o1] = h1;
        *(uint32_t*)&g_alo[o1] = l1w;
    }
}

// ---------------------------------------------------------------------------
// Launch
// ---------------------------------------------------------------------------
extern "C" void kernel_launch(void* const* d_in, const int* in_sizes, int n_in,
                              void* d_out, int out_size)
{
    const float* x  = (const float*)d_in[0];
    const float* wq = (const float*)d_in[2];
    const float* bq = (const float*)d_in[3];
    const float* wk = (const float*)d_in[4];
    const float* bk = (const float*)d_in[5];
    const float* wv = (const float*)d_in[6];
    const float* bv = (const float*)d_in[7];
    const float* wo = (const float*)d_in[8];
    const float* bo = (const float*)d_in[9];
    float* out = (float*)d_out;

    __nv_bfloat16 *ahi, *alo, *whi, *wlo, *qhi, *qlo, *khi, *klo;
    cudaGetSymbolAddress((void**)&ahi, g_ahi);
    cudaGetSymbolAddress((void**)&alo, g_alo);
    cudaGetSymbolAddress((void**)&whi, g_whi);
    cudaGetSymbolAddress((void**)&wlo, g_wlo);
    cudaGetSymbolAddress((void**)&qhi, g_qhi);
    cudaGetSymbolAddress((void**)&qlo, g_qlo);
    cudaGetSymbolAddress((void**)&khi, g_khi);
    cudaGetSymbolAddress((void**)&klo, g_klo);

    const size_t WSZ = (size_t)DDIM * DDIM;

    sincos_kernel<<<(TT * 32 + 255) / 256, 256>>>();

    const int n4 = MM * DDIM / 4;
    split_kernel<<<(n4 + 255) / 256, 256>>>(x, ahi, alo, n4);
    dim3 tgrid(32, 32), tblk(32, 8);
    splitT_kernel<<<tgrid, tblk>>>(wq, whi + 0 * WSZ, wlo + 0 * WSZ);
    splitT_kernel<<<tgrid, tblk>>>(wk, whi + 1 * WSZ, wlo + 1 * WSZ);
    splitT_kernel<<<tgrid, tblk>>>(wv, whi + 2 * WSZ, wlo + 2 * WSZ);
    splitT_kernel<<<tgrid, tblk>>>(wo, whi + 3 * WSZ, wlo + 3 * WSZ);

    cudaFuncSetAttribute(mma_gemm, cudaFuncAttributeMaxDynamicSharedMemorySize,
                         GEMM_SMEM);
    cudaFuncSetAttribute(mma_gemm_rope,
                         cudaFuncAttributeMaxDynamicSharedMemorySize, GEMM_SMEM);
    cudaFuncSetAttribute(mma_gemm_vt,
                         cudaFuncAttributeMaxDynamicSharedMemorySize, GEMM_SMEM);
    dim3 ggrid(DDIM / 128, MM / 128);

    // Q,K projections: fused bias+rope+split epilogue (smem-staged)
    mma_gemm_rope<<<ggrid, 256, GEMM_SMEM>>>(ahi, alo, whi + 0 * WSZ, wlo + 0 * WSZ,
                                             bq, qhi, qlo);
    mma_gemm_rope<<<ggrid, 256, GEMM_SMEM>>>(ahi, alo, whi + 1 * WSZ, wlo + 1 * WSZ,
                                             bk, khi, klo);
    // V projection: fused bias+transpose+split epilogue
    mma_gemm_vt<<<ggrid, 256, GEMM_SMEM>>>(ahi, alo, whi + 2 * WSZ, wlo + 2 * WSZ, bv);

    // tensor-core flash attention (writes ahi/alo directly)
    cudaFuncSetAttribute(attn_mma_kernel,
                         cudaFuncAttributeMaxDynamicSharedMemorySize, ATTN_SMEM);
    attn_mma_kernel<<<dim3(TT / 128, HH, BB), 256, ATTN_SMEM>>>();

    // out-projection
    mma_gemm<<<ggrid, 256, GEMM_SMEM>>>(ahi, alo, whi + 3 * WSZ, wlo + 3 * WSZ, bo, out);
}

// round 11
// speedup vs baseline: 2.0795x; 2.0450x over previous
#include <cuda_runtime.h>
#include <cuda_fp16.h>
#include <math.h>
#include <math_constants.h>
#include <cstdint>

// Problem constants
#define BB  2
#define TT  2048
#define DDIM 1024
#define HH  16
#define DHH 64
#define MM  (BB*TT)

// ---------------------------------------------------------------------------
// Scratch (device globals)
// ---------------------------------------------------------------------------
__device__ float g_sin[TT * 32];
__device__ float g_cos[TT * 32];

__device__ __half g_a[(size_t)MM * DDIM];        // activations fp16 (x, later attn out)
__device__ __half g_w[(size_t)4 * DDIM * DDIM];  // weights transposed [N,K] fp16
__device__ __half g_qh[(size_t)MM * DDIM];       // q after rope
__device__ __half g_kh[(size_t)MM * DDIM];       // k after rope
__device__ __half g_vt[(size_t)MM * DDIM];       // v transposed [b,h,dh,T]

// ---------------------------------------------------------------------------
// Warp tensor helpers (baseline PTX: ldmatrix + mma.sync + cp.async)
// ---------------------------------------------------------------------------
__device__ __forceinline__ uint32_t smem_u32(const void* p) {
    uint32_t a;
    asm("{ .reg .u64 t; cvta.to.shared.u64 t, %1; cvt.u32.u64 %0, t; }"
        : "=r"(a) : "l"(p));
    return a;
}

__device__ __forceinline__ void ldm_x4(uint32_t* r, uint32_t addr) {
    asm volatile("ldmatrix.sync.aligned.m8n8.x4.shared.b16 {%0,%1,%2,%3}, [%4];"
                 : "=r"(r[0]), "=r"(r[1]), "=r"(r[2]), "=r"(r[3]) : "r"(addr));
}

__device__ __forceinline__ void mma_h(float* c, const uint32_t* a,
                                      const uint32_t* b) {
    asm volatile(
        "mma.sync.aligned.m16n8k16.row.col.f32.f16.f16.f32 "
        "{%0,%1,%2,%3}, {%4,%5,%6,%7}, {%8,%9}, {%0,%1,%2,%3};"
        : "+f"(c[0]), "+f"(c[1]), "+f"(c[2]), "+f"(c[3])
        : "r"(a[0]), "r"(a[1]), "r"(a[2]), "r"(a[3]), "r"(b[0]), "r"(b[1]));
}

__device__ __forceinline__ void cp16(uint32_t dst, const void* src) {
    asm volatile("cp.async.cg.shared.global [%0], [%1], 16;"
                 :: "r"(dst), "l"(src));
}
#define CP_COMMIT() asm volatile("cp.async.commit_group;" ::: "memory")
#define CP_WAIT0()  asm volatile("cp.async.wait_group 0;" ::: "memory")

// pack 2 floats to f16x2: low half = first arg (mirrors proven bf16 helper)
__device__ __forceinline__ uint32_t cvt_h2(float lo, float hi) {
    uint32_t r;
    asm("cvt.rn.f16x2.f32 %0, %1, %2;" : "=r"(r) : "f"(hi), "f"(lo));
    return r;
}

// ---------------------------------------------------------------------------
// RoPE sin/cos table
// ---------------------------------------------------------------------------
__global__ void sincos_kernel() {
    int idx = blockIdx.x * blockDim.x + threadIdx.x;
    if (idx >= TT * 32) return;
    int t  = idx >> 5;
    int jj = idx & 31;
    double ang = (double)t * pow(10000.0, -2.0 * (double)jj / 64.0);
    g_sin[idx] = (float)sin(ang);
    g_cos[idx] = (float)cos(ang);
}

// ---------------------------------------------------------------------------
// fp32 -> fp16 convert (vectorized)
// ---------------------------------------------------------------------------
__global__ void conv_kernel(const float* __restrict__ src,
                            __half* __restrict__ dst, int n4) {
    int i = blockIdx.x * blockDim.x + threadIdx.x;
    if (i >= n4) return;
    float4 v = ((const float4*)src)[i];
    uint2 o;
    o.x = cvt_h2(v.x, v.y);
    o.y = cvt_h2(v.z, v.w);
    ((uint2*)dst)[i] = o;
}

// fp32 W[K,N] -> fp16 transposed [N,K]
__global__ void convT_kernel(const float* __restrict__ w,
                             __half* __restrict__ o) {
    __shared__ float tile[32][33];
    int bx = blockIdx.x * 32;
    int by = blockIdx.y * 32;
    int tx = threadIdx.x, ty = threadIdx.y;
#pragma unroll
    for (int i = 0; i < 32; i += 8)
        tile[ty + i][tx] = w[(size_t)(by + ty + i) * DDIM + bx + tx];
    __syncthreads();
#pragma unroll
    for (int i = 0; i < 32; i += 8)
        o[(size_t)(bx + ty + i) * DDIM + by + tx] = __float2half(tile[tx][ty + i]);
}

// ---------------------------------------------------------------------------
// Shared GEMM mainloop (proven shape: 8 warps, warp tile 64x32, kTile=32)
// fp16 single-pass operands.
// ---------------------------------------------------------------------------
#define GT_ROW 80        // bytes per smem row (40 halves: 32 data + 8 pad)
#define GT_ARR 10240     // bytes per tile array (128*80)
#define GT_BUF 20480     // bytes per stage (A + B)
#define GEMM_SMEM_MAIN (2 * GT_BUF)            // 40960
#define GEMM_SMEM_EPI  (128 * 129 * 4)         // 66048 fp32 staging

#define G_LOAD(kt, buf) do {                                                  \
        int k0_ = (kt) * 32;                                                  \
        _Pragma("unroll")                                                     \
        for (int half_ = 0; half_ < 2; half_++) {                             \
            int row_ = half_ * 64 + ld_row;                                   \
            size_t ga_ = (size_t)(bm + row_) * DDIM + k0_ + ld_cg;            \
            size_t gb_ = (size_t)(bn + row_) * DDIM + k0_ + ld_cg;            \
            uint32_t so_ = sb + (buf) * GT_BUF + row_ * GT_ROW + ld_cg * 2;   \
            cp16(so_, A + ga_);                                               \
            cp16(so_ + GT_ARR, Bw + gb_);                                     \
        } } while (0)

#define G_MAINLOOP()                                                          \
    G_LOAD(0, 0);                                                             \
    CP_COMMIT();                                                              \
    for (int kt = 0; kt < 32; kt++) {                                         \
        CP_WAIT0();                                                           \
        __syncthreads();                                                      \
        if (kt + 1 < 32) { G_LOAD(kt + 1, (kt + 1) & 1); CP_COMMIT(); }       \
        const uint32_t bufb = sb + (kt & 1) * GT_BUF;                         \
        _Pragma("unroll")                                                     \
        for (int ko = 0; ko < 32; ko += 16) {                                 \
            uint32_t bfr[4][2];                                               \
            _Pragma("unroll")                                                 \
            for (int p = 0; p < 2; p++) {                                     \
                uint32_t t4[4];                                               \
                uint32_t boff = (wn + p * 16 + b_n) * GT_ROW + (ko + b_kof) * 2; \
                ldm_x4(t4, bufb + GT_ARR + boff);                             \
                bfr[p * 2][0] = t4[0]; bfr[p * 2][1] = t4[1];                 \
                bfr[p * 2 + 1][0] = t4[2]; bfr[p * 2 + 1][1] = t4[3];         \
            }                                                                 \
            _Pragma("unroll")                                                 \
            for (int mf = 0; mf < 4; mf++) {                                  \
                uint32_t ar[4];                                               \
                uint32_t aoff = (wm + mf * 16 + a_row) * GT_ROW + (ko + a_kof) * 2; \
                ldm_x4(ar, bufb + aoff);                                      \
                _Pragma("unroll")                                             \
                for (int nf = 0; nf < 4; nf++)                                \
                    mma_h(acc[mf][nf], ar, bfr[nf]);                          \
            }                                                                 \
        }                                                                     \
        __syncthreads();                                                      \
    }

#define G_PROLOG()                                                            \
    extern __shared__ char gsm[];                                             \
    const uint32_t sb = smem_u32(gsm);                                        \
    const int tid = threadIdx.x;                                              \
    const int lane = tid & 31;                                                \
    const int wid = tid >> 5;                                                 \
    const int wm = (wid & 1) * 64;                                            \
    const int wn = (wid >> 1) * 32;                                           \
    const int bn = blockIdx.x * 128;                                          \
    const int bm = blockIdx.y * 128;                                          \
    float acc[4][4][4];                                                       \
    _Pragma("unroll")                                                         \
    for (int i = 0; i < 4; i++)                                               \
        _Pragma("unroll")                                                     \
        for (int j = 0; j < 4; j++)                                           \
            _Pragma("unroll")                                                 \
            for (int r = 0; r < 4; r++) acc[i][j][r] = 0.f;                   \
    const int a_row = lane & 15;                                              \
    const int a_kof = (lane >> 4) << 3;                                       \
    const int b_n   = (lane & 7) + ((lane >> 4) << 3);                        \
    const int b_kof = ((lane >> 3) & 1) << 3;                                 \
    const int ld_row = tid >> 2;                                              \
    const int ld_cg  = (tid & 3) * 8;

// Store acc + bias into fp32 staging smem [128][129]
#define G_STAGE_SMEM()                                                        \
    float* Ssm = (float*)gsm;                                                 \
    {                                                                         \
        const int qr = lane >> 2;                                             \
        const int qc = (lane & 3) * 2;                                        \
        _Pragma("unroll")                                                     \
        for (int mf = 0; mf < 4; mf++) {                                      \
            _Pragma("unroll")                                                 \
            for (int nf = 0; nf < 4; nf++) {                                  \
                int row = wm + mf * 16 + qr;                                  \
                int col = wn + nf * 8 + qc;                                   \
                float b0 = bias[bn + col], b1 = bias[bn + col + 1];           \
                Ssm[row * 129 + col]     = acc[mf][nf][0] + b0;               \
                Ssm[row * 129 + col + 1] = acc[mf][nf][1] + b1;               \
                Ssm[(row + 8) * 129 + col]     = acc[mf][nf][2] + b0;         \
                Ssm[(row + 8) * 129 + col + 1] = acc[mf][nf][3] + b1;         \
            }                                                                 \
        }                                                                     \
    }                                                                         \
    __syncthreads();

// ---------------------------------------------------------------------------
// Plain GEMM: fp32 output + bias (out-projection)
// ---------------------------------------------------------------------------
__global__ void __launch_bounds__(256) mma_gemm(
    const __half* __restrict__ A, const __half* __restrict__ Bw,
    const float* __restrict__ bias, float* __restrict__ C)
{
    G_PROLOG();
    G_MAINLOOP();

    const int qr = lane >> 2;
    const int qc = (lane & 3) * 2;
#pragma unroll
    for (int mf = 0; mf < 4; mf++) {
#pragma unroll
        for (int nf = 0; nf < 4; nf++) {
            int col = bn + wn + nf * 8 + qc;
            float b0 = bias[col], b1 = bias[col + 1];
            int r0 = bm + wm + mf * 16 + qr;
            float2 v0 = {acc[mf][nf][0] + b0, acc[mf][nf][1] + b1};
            float2 v1 = {acc[mf][nf][2] + b0, acc[mf][nf][3] + b1};
            *(float2*)&C[(size_t)r0 * DDIM + col] = v0;
            *(float2*)&C[(size_t)(r0 + 8) * DDIM + col] = v1;
        }
    }
}

// ---------------------------------------------------------------------------
// Q/K GEMM: smem-staged epilogue, fused bias + RoPE, fp16 output
// ---------------------------------------------------------------------------
__global__ void __launch_bounds__(256) mma_gemm_rope(
    const __half* __restrict__ A, const __half* __restrict__ Bw,
    const float* __restrict__ bias, __half* __restrict__ O)
{
    G_PROLOG();
    G_MAINLOOP();
    G_STAGE_SMEM();

    // 128 rows x 2 heads x 32 pairs = 8192 rope pairs
    for (int p = tid; p < 8192; p += 256) {
        int j  = p & 31;
        int hh = (p >> 5) & 1;
        int m  = p >> 6;
        int gm = bm + m;
        int t  = gm & (TT - 1);
        int cb = hh * 64;
        float a  = Ssm[m * 129 + cb + j];
        float bv = Ssm[m * 129 + cb + j + 32];
        int jj = j >> 1;
        float c1 = g_cos[t * 32 + jj],      s1 = g_sin[t * 32 + jj];
        float c2 = g_cos[t * 32 + jj + 16], s2 = g_sin[t * 32 + jj + 16];
        float o0 = a * c1 - bv * s1;
        float o1 = bv * c2 + a * s2;
        size_t off = (size_t)gm * DDIM + bn + cb + j;
        O[off]      = __float2half(o0);
        O[off + 32] = __float2half(o1);
    }
}

// ---------------------------------------------------------------------------
// V GEMM: smem-staged epilogue, fused bias + transpose, fp16 output
// to g_vt[b,h,dh,T] with T-coalesced writes.
// ---------------------------------------------------------------------------
__global__ void __launch_bounds__(256) mma_gemm_vt(
    const __half* __restrict__ A, const __half* __restrict__ Bw,
    const float* __restrict__ bias)
{
    G_PROLOG();
    G_MAINLOOP();
    G_STAGE_SMEM();

    const int bq_ = bm >> 11;           // batch index
    const int tm  = bm & (TT - 1);      // T-offset within batch
#pragma unroll
    for (int ci = 0; ci < 16; ci++) {
        int c = wid + ci * 8;
        int gcol = bn + c;
        int hh = gcol >> 6, d = gcol & 63;
        size_t obase = ((size_t)(bq_ * HH + hh) * DHH + d) * TT + tm;
#pragma unroll
        for (int rj = 0; rj < 4; rj++) {
            int row = lane + rj * 32;
            g_vt[obase + row] = __float2half(Ssm[row * 129 + c]);
        }
    }
}

// ---------------------------------------------------------------------------
// Flash attention, fp16 single-pass, cp.async double-buffered K/V staging.
// Block: 128 q-rows x (b,h). 8 warps, each m16. k-tiles of 64.
// Epilogue writes fp16 directly into g_a (feeds out-proj).
// ---------------------------------------------------------------------------
#define AT_ROW 144       // bytes per smem row (72 halves: 64 data + 8 pad)
#define AT_ARR 9216      // bytes per array (64*144)
#define AT_BUF 18432     // K + V per stage
#define ATTN_SMEM (2 * AT_BUF)   // 36864 (Q staging reuses [0,18432))

__global__ void __launch_bounds__(256) attn_mma_kernel() {
    extern __shared__ char gsm[];
    const uint32_t sb = smem_u32(gsm);

    const int q0 = blockIdx.x * 128;
    const int h  = blockIdx.y;
    const int b  = blockIdx.z;
    const int tid = threadIdx.x;
    const int lane = tid & 31;
    const int wid = tid >> 5;
    const int wm = wid * 16;

    const size_t base_qk = (size_t)b * TT * DDIM + (size_t)h * DHH;
    const size_t base_vt = ((size_t)(b * HH + h)) * DHH * TT;

    const int a_row = lane & 15;
    const int a_kof = (lane >> 4) << 3;
    const int b_n   = (lane & 7) + ((lane >> 4) << 3);
    const int b_kof = ((lane >> 3) & 1) << 3;

    // ---- stage Q tile, load Q frags to registers ----
    for (int i = tid; i < 128 * 8; i += 256) {
        int r = i >> 3, c = (i & 7) * 8;
        size_t g = base_qk + (size_t)(q0 + r) * DDIM + c;
        *(uint4*)(gsm + r * AT_ROW + c * 2) = *(const uint4*)&g_qh[g];
    }
    __syncthreads();

    uint32_t qf[4][4];
#pragma unroll
    for (int ko = 0; ko < 4; ko++) {
        uint32_t aoff = (wm + a_row) * AT_ROW + (ko * 16 + a_kof) * 2;
        ldm_x4(qf[ko], sb + aoff);
    }
    __syncthreads();  // Q smem consumed; region reused by K/V stages

    float m0 = -CUDART_INF_F, m1 = -CUDART_INF_F;
    float l0 = 0.f, l1 = 0.f;
    float o[8][4];
#pragma unroll
    for (int nf = 0; nf < 8; nf++)
#pragma unroll
        for (int r = 0; r < 4; r++) o[nf][r] = 0.f;

    const int nkt = q0 / 64 + 2;
    const float scale = 0.125f;

#define A_LOAD(kt, buf) do {                                                  \
        int k0_ = (kt) * 64;                                                  \
        _Pragma("unroll")                                                     \
        for (int i = tid; i < 512; i += 256) {                                \
            int r_ = i >> 3, c_ = (i & 7) * 8;                                \
            uint32_t so_ = sb + (buf) * AT_BUF + r_ * AT_ROW + c_ * 2;        \
            size_t gk_ = base_qk + (size_t)(k0_ + r_) * DDIM + c_;            \
            size_t gv_ = base_vt + (size_t)r_ * TT + k0_ + c_;                \
            cp16(so_, g_kh + gk_);                                            \
            cp16(so_ + AT_ARR, g_vt + gv_);                                   \
        } } while (0)

    A_LOAD(0, 0);
    CP_COMMIT();

    for (int kt = 0; kt < nkt; kt++) {
        const int k0 = kt * 64;
        CP_WAIT0();
        __syncthreads();
        if (kt + 1 < nkt) { A_LOAD(kt + 1, (kt + 1) & 1); CP_COMMIT(); }

        const uint32_t bufb = sb + (kt & 1) * AT_BUF;

        if (k0 <= q0 + wm + 15) {
            // ---- S = Q K^T ----
            float s[8][4];
#pragma unroll
            for (int nf = 0; nf < 8; nf++)
#pragma unroll
                for (int r = 0; r < 4; r++) s[nf][r] = 0.f;

#pragma unroll
            for (int ko = 0; ko < 4; ko++) {
#pragma unroll
                for (int p = 0; p < 4; p++) {
                    uint32_t th[4];
                    uint32_t boff = (p * 16 + b_n) * AT_ROW + (ko * 16 + b_kof) * 2;
                    ldm_x4(th, bufb + boff);
                    mma_h(s[2 * p],     qf[ko], th);
                    mma_h(s[2 * p + 1], qf[ko], th + 2);
                }
            }

            // ---- scale + causal mask ----
            const int qa = q0 + wm + (lane >> 2);
            const int qb = qa + 8;
            const bool need_mask = (k0 + 63 > q0 + wm);
#pragma unroll
            for (int nf = 0; nf < 8; nf++) {
                int cg = k0 + nf * 8 + (lane & 3) * 2;
                s[nf][0] *= scale; s[nf][1] *= scale;
                s[nf][2] *= scale; s[nf][3] *= scale;
                if (need_mask) {
                    if (cg > qa)     s[nf][0] = -10000.f;
                    if (cg + 1 > qa) s[nf][1] = -10000.f;
                    if (cg > qb)     s[nf][2] = -10000.f;
                    if (cg + 1 > qb) s[nf][3] = -10000.f;
                }
            }

            // ---- online softmax ----
            float rma = -CUDART_INF_F, rmb = -CUDART_INF_F;
#pragma unroll
            for (int nf = 0; nf < 8; nf++) {
                rma = fmaxf(rma, fmaxf(s[nf][0], s[nf][1]));
                rmb = fmaxf(rmb, fmaxf(s[nf][2], s[nf][3]));
            }
            rma = fmaxf(rma, __shfl_xor_sync(0xffffffffu, rma, 1));
            rma = fmaxf(rma, __shfl_xor_sync(0xffffffffu, rma, 2));
            rmb = fmaxf(rmb, __shfl_xor_sync(0xffffffffu, rmb, 1));
            rmb = fmaxf(rmb, __shfl_xor_sync(0xffffffffu, rmb, 2));
            float nma = fmaxf(m0, rma), nmb = fmaxf(m1, rmb);
            float alpha_a = __expf(m0 - nma), alpha_b = __expf(m1 - nmb);
            m0 = nma; m1 = nmb;

            float rsa = 0.f, rsb = 0.f;
#pragma unroll
            for (int nf = 0; nf < 8; nf++) {
                s[nf][0] = __expf(s[nf][0] - nma);
                s[nf][1] = __expf(s[nf][1] - nma);
                s[nf][2] = __expf(s[nf][2] - nmb);
                s[nf][3] = __expf(s[nf][3] - nmb);
                rsa += s[nf][0] + s[nf][1];
                rsb += s[nf][2] + s[nf][3];
            }
            rsa += __shfl_xor_sync(0xffffffffu, rsa, 1);
            rsa += __shfl_xor_sync(0xffffffffu, rsa, 2);
            rsb += __shfl_xor_sync(0xffffffffu, rsb, 1);
            rsb += __shfl_xor_sync(0xffffffffu, rsb, 2);
            l0 = l0 * alpha_a + rsa;
            l1 = l1 * alpha_b + rsb;

#pragma unroll
            for (int nf = 0; nf < 8; nf++) {
                o[nf][0] *= alpha_a; o[nf][1] *= alpha_a;
                o[nf][2] *= alpha_b; o[nf][3] *= alpha_b;
            }

            // ---- P fragments (fp16) from S fragments ----
            uint32_t ph[4][4];
#pragma unroll
            for (int kb = 0; kb < 4; kb++) {
                float* f0 = s[2 * kb];
                float* f1 = s[2 * kb + 1];
                ph[kb][0] = cvt_h2(f0[0], f0[1]);
                ph[kb][1] = cvt_h2(f0[2], f0[3]);
                ph[kb][2] = cvt_h2(f1[0], f1[1]);
                ph[kb][3] = cvt_h2(f1[2], f1[3]);
            }

            // ---- O += P V ----
#pragma unroll
            for (int kb = 0; kb < 4; kb++) {
#pragma unroll
                for (int p = 0; p < 4; p++) {
                    uint32_t th[4];
                    uint32_t boff = (p * 16 + b_n) * AT_ROW + (kb * 16 + b_kof) * 2;
                    ldm_x4(th, bufb + AT_ARR + boff);
                    mma_h(o[2 * p],     ph[kb], th);
                    mma_h(o[2 * p + 1], ph[kb], th + 2);
                }
            }
        }
        __syncthreads();
    }
#undef A_LOAD

    // ---- epilogue: normalize + write fp16 directly into g_a ----
    float inv_a = 1.0f / l0, inv_b = 1.0f / l1;
    int ra = q0 + wm + (lane >> 2);
    int cq = (lane & 3) * 2;
#pragma unroll
    for (int nf = 0; nf < 8; nf++) {
        int col = h * DHH + nf * 8 + cq;
        float v0 = o[nf][0] * inv_a, v1 = o[nf][1] * inv_a;
        float v2 = o[nf][2] * inv_b, v3 = o[nf][3] * inv_b;
        size_t o0 = ((size_t)b * TT + ra) * DDIM + col;
        size_t o1 = ((size_t)b * TT + ra + 8) * DDIM + col;
        *(uint32_t*)&g_a[o0] = cvt_h2(v0, v1);
        *(uint32_t*)&g_a[o1] = cvt_h2(v2, v3);
    }
}

// ---------------------------------------------------------------------------
// Launch
// ---------------------------------------------------------------------------
extern "C" void kernel_launch(void* const* d_in, const int* in_sizes, int n_in,
                              void* d_out, int out_size)
{
    const float* x  = (const float*)d_in[0];
    const float* wq = (const float*)d_in[2];
    const float* bq = (const float*)d_in[3];
    const float* wk = (const float*)d_in[4];
    const float* bk = (const float*)d_in[5];
    const float* wv = (const float*)d_in[6];
    const float* bv = (const float*)d_in[7];
    const float* wo = (const float*)d_in[8];
    const float* bo = (const float*)d_in[9];
    float* out = (float*)d_out;

    __half *ap, *wp, *qp, *kp;
    cudaGetSymbolAddress((void**)&ap, g_a);
    cudaGetSymbolAddress((void**)&wp, g_w);
    cudaGetSymbolAddress((void**)&qp, g_qh);
    cudaGetSymbolAddress((void**)&kp, g_kh);

    const size_t WSZ = (size_t)DDIM * DDIM;

    sincos_kernel<<<(TT * 32 + 255) / 256, 256>>>();

    const int n4 = MM * DDIM / 4;
    conv_kernel<<<(n4 + 255) / 256, 256>>>(x, ap, n4);
    dim3 tgrid(32, 32), tblk(32, 8);
    convT_kernel<<<tgrid, tblk>>>(wq, wp + 0 * WSZ);
    convT_kernel<<<tgrid, tblk>>>(wk, wp + 1 * WSZ);
    convT_kernel<<<tgrid, tblk>>>(wv, wp + 2 * WSZ);
    convT_kernel<<<tgrid, tblk>>>(wo, wp + 3 * WSZ);

    cudaFuncSetAttribute(mma_gemm, cudaFuncAttributeMaxDynamicSharedMemorySize,
                         GEMM_SMEM_MAIN);
    cudaFuncSetAttribute(mma_gemm_rope,
                         cudaFuncAttributeMaxDynamicSharedMemorySize, GEMM_SMEM_EPI);
    cudaFuncSetAttribute(mma_gemm_vt,
                         cudaFuncAttributeMaxDynamicSharedMemorySize, GEMM_SMEM_EPI);
    dim3 ggrid(DDIM / 128, MM / 128);

    // Q,K projections: fused bias + rope epilogue, fp16 out
    mma_gemm_rope<<<ggrid, 256, GEMM_SMEM_EPI>>>(ap, wp + 0 * WSZ, bq, qp);
    mma_gemm_rope<<<ggrid, 256, GEMM_SMEM_EPI>>>(ap, wp + 1 * WSZ, bk, kp);
    // V projection: fused bias + transpose epilogue, fp16 out
    mma_gemm_vt<<<ggrid, 256, GEMM_SMEM_EPI>>>(ap, wp + 2 * WSZ, bv);

    // flash attention (overwrites g_a with fp16 attention output)
    cudaFuncSetAttribute(attn_mma_kernel,
                         cudaFuncAttributeMaxDynamicSharedMemorySize, ATTN_SMEM);
    attn_mma_kernel<<<dim3(TT / 128, HH, BB), 256, ATTN_SMEM>>>();

    // out-projection -> fp32 output
    mma_gemm<<<ggrid, 256, GEMM_SMEM_MAIN>>>(ap, wp + 3 * WSZ, bo, out);
}

// round 12
// speedup vs baseline: 2.2314x; 1.0731x over previous
#include <cuda_runtime.h>
#include <cuda_fp16.h>
#include <math.h>
#include <math_constants.h>
#include <cstdint>

// Problem constants
#define BB  2
#define TT  2048
#define DDIM 1024
#define HH  16
#define DHH 64
#define MM  (BB*TT)

// ---------------------------------------------------------------------------
// Scratch (device globals)
// ---------------------------------------------------------------------------
__device__ float g_sin[TT * 32];
__device__ float g_cos[TT * 32];

__device__ __half g_a[(size_t)MM * DDIM];        // activations fp16 (x, later attn out)
__device__ __half g_w[(size_t)4 * DDIM * DDIM];  // weights transposed [N,K] fp16
__device__ __half g_qh[(size_t)MM * DDIM];       // q after rope
__device__ __half g_kh[(size_t)MM * DDIM];       // k after rope
__device__ __half g_vt[(size_t)MM * DDIM];       // v transposed [b,h,dh,T]

// ---------------------------------------------------------------------------
// Warp tensor helpers (baseline PTX: ldmatrix + mma.sync + cp.async)
// ---------------------------------------------------------------------------
__device__ __forceinline__ uint32_t smem_u32(const void* p) {
    uint32_t a;
    asm("{ .reg .u64 t; cvta.to.shared.u64 t, %1; cvt.u32.u64 %0, t; }"
        : "=r"(a) : "l"(p));
    return a;
}

__device__ __forceinline__ void ldm_x4(uint32_t* r, uint32_t addr) {
    asm volatile("ldmatrix.sync.aligned.m8n8.x4.shared.b16 {%0,%1,%2,%3}, [%4];"
                 : "=r"(r[0]), "=r"(r[1]), "=r"(r[2]), "=r"(r[3]) : "r"(addr));
}

__device__ __forceinline__ void mma_h(float* c, const uint32_t* a,
                                      const uint32_t* b) {
    asm volatile(
        "mma.sync.aligned.m16n8k16.row.col.f32.f16.f16.f32 "
        "{%0,%1,%2,%3}, {%4,%5,%6,%7}, {%8,%9}, {%0,%1,%2,%3};"
        : "+f"(c[0]), "+f"(c[1]), "+f"(c[2]), "+f"(c[3])
        : "r"(a[0]), "r"(a[1]), "r"(a[2]), "r"(a[3]), "r"(b[0]), "r"(b[1]));
}

__device__ __forceinline__ void cp16(uint32_t dst, const void* src) {
    asm volatile("cp.async.cg.shared.global [%0], [%1], 16;"
                 :: "r"(dst), "l"(src));
}
#define CP_COMMIT() asm volatile("cp.async.commit_group;" ::: "memory")
#define CP_WAIT0()  asm volatile("cp.async.wait_group 0;" ::: "memory")

// pack 2 floats to f16x2: low half = first arg
__device__ __forceinline__ uint32_t cvt_h2(float lo, float hi) {
    uint32_t r;
    asm("cvt.rn.f16x2.f32 %0, %1, %2;" : "=r"(r) : "f"(hi), "f"(lo));
    return r;
}

// ---------------------------------------------------------------------------
// RoPE sin/cos table
// ---------------------------------------------------------------------------
__global__ void sincos_kernel() {
    int idx = blockIdx.x * blockDim.x + threadIdx.x;
    if (idx >= TT * 32) return;
    int t  = idx >> 5;
    int jj = idx & 31;
    double ang = (double)t * pow(10000.0, -2.0 * (double)jj / 64.0);
    g_sin[idx] = (float)sin(ang);
    g_cos[idx] = (float)cos(ang);
}

// ---------------------------------------------------------------------------
// fp32 -> fp16 convert (vectorized)
// ---------------------------------------------------------------------------
__global__ void conv_kernel(const float* __restrict__ src,
                            __half* __restrict__ dst, int n4) {
    int i = blockIdx.x * blockDim.x + threadIdx.x;
    if (i >= n4) return;
    float4 v = ((const float4*)src)[i];
    uint2 o;
    o.x = cvt_h2(v.x, v.y);
    o.y = cvt_h2(v.z, v.w);
    ((uint2*)dst)[i] = o;
}

// fp32 W[K,N] -> fp16 transposed [N,K]; all 4 weights in one launch (z)
__global__ void convT_kernel(const float* __restrict__ w0,
                             const float* __restrict__ w1,
                             const float* __restrict__ w2,
                             const float* __restrict__ w3) {
    __shared__ float tile[32][33];
    int z = blockIdx.z;
    const float* w = (z == 0) ? w0 : (z == 1) ? w1 : (z == 2) ? w2 : w3;
    __half* o = g_w + (size_t)z * DDIM * DDIM;
    int bx = blockIdx.x * 32;
    int by = blockIdx.y * 32;
    int tx = threadIdx.x, ty = threadIdx.y;
#pragma unroll
    for (int i = 0; i < 32; i += 8)
        tile[ty + i][tx] = w[(size_t)(by + ty + i) * DDIM + bx + tx];
    __syncthreads();
#pragma unroll
    for (int i = 0; i < 32; i += 8)
        o[(size_t)(bx + ty + i) * DDIM + by + tx] = __float2half(tile[tx][ty + i]);
}

// ---------------------------------------------------------------------------
// Shared GEMM mainloop (8 warps, warp tile 64x32, kTile=32), fp16 single-pass
// ---------------------------------------------------------------------------
#define GT_ROW 80
#define GT_ARR 10240
#define GT_BUF 20480
#define GEMM_SMEM_MAIN (2 * GT_BUF)            // 40960
#define GEMM_SMEM_EPI  (128 * 129 * 4)         // 66048 fp32 staging

#define G_LOAD(kt, buf) do {                                                  \
        int k0_ = (kt) * 32;                                                  \
        _Pragma("unroll")                                                     \
        for (int half_ = 0; half_ < 2; half_++) {                             \
            int row_ = half_ * 64 + ld_row;                                   \
            size_t ga_ = (size_t)(bm + row_) * DDIM + k0_ + ld_cg;            \
            size_t gb_ = (size_t)(bn + row_) * DDIM + k0_ + ld_cg;            \
            uint32_t so_ = sb + (buf) * GT_BUF + row_ * GT_ROW + ld_cg * 2;   \
            cp16(so_, A + ga_);                                               \
            cp16(so_ + GT_ARR, Bw + gb_);                                     \
        } } while (0)

#define G_MAINLOOP()                                                          \
    G_LOAD(0, 0);                                                             \
    CP_COMMIT();                                                              \
    for (int kt = 0; kt < 32; kt++) {                                         \
        CP_WAIT0();                                                           \
        __syncthreads();                                                      \
        if (kt + 1 < 32) { G_LOAD(kt + 1, (kt + 1) & 1); CP_COMMIT(); }       \
        const uint32_t bufb = sb + (kt & 1) * GT_BUF;                         \
        _Pragma("unroll")                                                     \
        for (int ko = 0; ko < 32; ko += 16) {                                 \
            uint32_t bfr[4][2];                                               \
            _Pragma("unroll")                                                 \
            for (int p = 0; p < 2; p++) {                                     \
                uint32_t t4[4];                                               \
                uint32_t boff = (wn + p * 16 + b_n) * GT_ROW + (ko + b_kof) * 2; \
                ldm_x4(t4, bufb + GT_ARR + boff);                             \
                bfr[p * 2][0] = t4[0]; bfr[p * 2][1] = t4[1];                 \
                bfr[p * 2 + 1][0] = t4[2]; bfr[p * 2 + 1][1] = t4[3];         \
            }                                                                 \
            _Pragma("unroll")                                                 \
            for (int mf = 0; mf < 4; mf++) {                                  \
                uint32_t ar[4];                                               \
                uint32_t aoff = (wm + mf * 16 + a_row) * GT_ROW + (ko + a_kof) * 2; \
                ldm_x4(ar, bufb + aoff);                                      \
                _Pragma("unroll")                                             \
                for (int nf = 0; nf < 4; nf++)                                \
                    mma_h(acc[mf][nf], ar, bfr[nf]);                          \
            }                                                                 \
        }                                                                     \
        __syncthreads();                                                      \
    }

#define G_PROLOG_BODY()                                                       \
    extern __shared__ char gsm[];                                             \
    const uint32_t sb = smem_u32(gsm);                                        \
    const int tid = threadIdx.x;                                              \
    const int lane = tid & 31;                                                \
    const int wid = tid >> 5;                                                 \
    const int wm = (wid & 1) * 64;                                            \
    const int wn = (wid >> 1) * 32;                                           \
    const int bn = blockIdx.x * 128;                                          \
    const int bm = blockIdx.y * 128;                                          \
    float acc[4][4][4];                                                       \
    _Pragma("unroll")                                                         \
    for (int i = 0; i < 4; i++)                                               \
        _Pragma("unroll")                                                     \
        for (int j = 0; j < 4; j++)                                           \
            _Pragma("unroll")                                                 \
            for (int r = 0; r < 4; r++) acc[i][j][r] = 0.f;                   \
    const int a_row = lane & 15;                                              \
    const int a_kof = (lane >> 4) << 3;                                       \
    const int b_n   = (lane & 7) + ((lane >> 4) << 3);                        \
    const int b_kof = ((lane >> 3) & 1) << 3;                                 \
    const int ld_row = tid >> 2;                                              \
    const int ld_cg  = (tid & 3) * 8;

// Store acc + bias into fp32 staging smem [128][129]
#define G_STAGE_SMEM()                                                        \
    float* Ssm = (float*)gsm;                                                 \
    {                                                                         \
        const int qr = lane >> 2;                                             \
        const int qc = (lane & 3) * 2;                                        \
        _Pragma("unroll")                                                     \
        for (int mf = 0; mf < 4; mf++) {                                      \
            _Pragma("unroll")                                                 \
            for (int nf = 0; nf < 4; nf++) {                                  \
                int row = wm + mf * 16 + qr;                                  \
                int col = wn + nf * 8 + qc;                                   \
                float b0 = bias[bn + col], b1 = bias[bn + col + 1];           \
                Ssm[row * 129 + col]     = acc[mf][nf][0] + b0;               \
                Ssm[row * 129 + col + 1] = acc[mf][nf][1] + b1;               \
                Ssm[(row + 8) * 129 + col]     = acc[mf][nf][2] + b0;         \
                Ssm[(row + 8) * 129 + col + 1] = acc[mf][nf][3] + b1;         \
            }                                                                 \
        }                                                                     \
    }                                                                         \
    __syncthreads();

// ---------------------------------------------------------------------------
// Fused QKV projection: grid (8, 32, 3); z selects weight slab + epilogue.
// z=0 -> Q (rope -> g_qh), z=1 -> K (rope -> g_kh), z=2 -> V (vt -> g_vt).
// One launch packs all 768 blocks into contiguous waves (no inter-GEMM drain).
// ---------------------------------------------------------------------------
__global__ void __launch_bounds__(256, 2) mma_gemm_qkv(
    const __half* __restrict__ A,
    const float* __restrict__ bqv, const float* __restrict__ bkv,
    const float* __restrict__ bvv)
{
    const int z = blockIdx.z;
    const __half* Bw = g_w + (size_t)z * DDIM * DDIM;
    const float* bias = (z == 0) ? bqv : (z == 1) ? bkv : bvv;

    G_PROLOG_BODY();
    G_MAINLOOP();
    G_STAGE_SMEM();

    if (z < 2) {
        // ---- rope epilogue -> g_qh / g_kh ----
        __half* O = (z == 0) ? g_qh : g_kh;
        for (int p = tid; p < 8192; p += 256) {
            int j  = p & 31;
            int hh = (p >> 5) & 1;
            int m  = p >> 6;
            int gm = bm + m;
            int t  = gm & (TT - 1);
            int cb = hh * 64;
            float a  = Ssm[m * 129 + cb + j];
            float bv = Ssm[m * 129 + cb + j + 32];
            int jj = j >> 1;
            float c1 = g_cos[t * 32 + jj],      s1 = g_sin[t * 32 + jj];
            float c2 = g_cos[t * 32 + jj + 16], s2 = g_sin[t * 32 + jj + 16];
            float o0 = a * c1 - bv * s1;
            float o1 = bv * c2 + a * s2;
            size_t off = (size_t)gm * DDIM + bn + cb + j;
            O[off]      = __float2half(o0);
            O[off + 32] = __float2half(o1);
        }
    } else {
        // ---- vt epilogue: transpose -> g_vt[b,h,dh,T] ----
        const int bq_ = bm >> 11;
        const int tm  = bm & (TT - 1);
#pragma unroll
        for (int ci = 0; ci < 16; ci++) {
            int c = wid + ci * 8;
            int gcol = bn + c;
            int hh = gcol >> 6, d = gcol & 63;
            size_t obase = ((size_t)(bq_ * HH + hh) * DHH + d) * TT + tm;
#pragma unroll
            for (int rj = 0; rj < 4; rj++) {
                int row = lane + rj * 32;
                g_vt[obase + row] = __float2half(Ssm[row * 129 + c]);
            }
        }
    }
}

// ---------------------------------------------------------------------------
// Plain GEMM: fp32 output + bias (out-projection)
// ---------------------------------------------------------------------------
__global__ void __launch_bounds__(256, 2) mma_gemm(
    const __half* __restrict__ A, const __half* __restrict__ Bw,
    const float* __restrict__ bias, float* __restrict__ C)
{
    G_PROLOG_BODY();
    G_MAINLOOP();

    const int qr = lane >> 2;
    const int qc = (lane & 3) * 2;
#pragma unroll
    for (int mf = 0; mf < 4; mf++) {
#pragma unroll
        for (int nf = 0; nf < 4; nf++) {
            int col = bn + wn + nf * 8 + qc;
            float b0 = bias[col], b1 = bias[col + 1];
            int r0 = bm + wm + mf * 16 + qr;
            float2 v0 = {acc[mf][nf][0] + b0, acc[mf][nf][1] + b1};
            float2 v1 = {acc[mf][nf][2] + b0, acc[mf][nf][3] + b1};
            *(float2*)&C[(size_t)r0 * DDIM + col] = v0;
            *(float2*)&C[(size_t)(r0 + 8) * DDIM + col] = v1;
        }
    }
}

// ---------------------------------------------------------------------------
// Flash attention, fp16 single-pass, cp.async double-buffered K/V staging.
// Heavy-first order: q0 reversed so longest blocks launch first.
// ---------------------------------------------------------------------------
#define AT_ROW 144
#define AT_ARR 9216
#define AT_BUF 18432
#define ATTN_SMEM (2 * AT_BUF)

__global__ void __launch_bounds__(256) attn_mma_kernel() {
    extern __shared__ char gsm[];
    const uint32_t sb = smem_u32(gsm);

    const int q0 = (gridDim.x - 1 - blockIdx.x) * 128;  // heavy blocks first
    const int h  = blockIdx.y;
    const int b  = blockIdx.z;
    const int tid = threadIdx.x;
    const int lane = tid & 31;
    const int wid = tid >> 5;
    const int wm = wid * 16;

    const size_t base_qk = (size_t)b * TT * DDIM + (size_t)h * DHH;
    const size_t base_vt = ((size_t)(b * HH + h)) * DHH * TT;

    const int a_row = lane & 15;
    const int a_kof = (lane >> 4) << 3;
    const int b_n   = (lane & 7) + ((lane >> 4) << 3);
    const int b_kof = ((lane >> 3) & 1) << 3;

    // ---- stage Q tile, load Q frags to registers ----
    for (int i = tid; i < 128 * 8; i += 256) {
        int r = i >> 3, c = (i & 7) * 8;
        size_t g = base_qk + (size_t)(q0 + r) * DDIM + c;
        *(uint4*)(gsm + r * AT_ROW + c * 2) = *(const uint4*)&g_qh[g];
    }
    __syncthreads();

    uint32_t qf[4][4];
#pragma unroll
    for (int ko = 0; ko < 4; ko++) {
        uint32_t aoff = (wm + a_row) * AT_ROW + (ko * 16 + a_kof) * 2;
        ldm_x4(qf[ko], sb + aoff);
    }
    __syncthreads();

    float m0 = -CUDART_INF_F, m1 = -CUDART_INF_F;
    float l0 = 0.f, l1 = 0.f;
    float o[8][4];
#pragma unroll
    for (int nf = 0; nf < 8; nf++)
#pragma unroll
        for (int r = 0; r < 4; r++) o[nf][r] = 0.f;

    const int nkt = q0 / 64 + 2;
    const float scale = 0.125f;

#define A_LOAD(kt, buf) do {                                                  \
        int k0_ = (kt) * 64;                                                  \
        _Pragma("unroll")                                                     \
        for (int i = tid; i < 512; i += 256) {                                \
            int r_ = i >> 3, c_ = (i & 7) * 8;                                \
            uint32_t so_ = sb + (buf) * AT_BUF + r_ * AT_ROW + c_ * 2;        \
            size_t gk_ = base_qk + (size_t)(k0_ + r_) * DDIM + c_;            \
            size_t gv_ = base_vt + (size_t)r_ * TT + k0_ + c_;                \
            cp16(so_, g_kh + gk_);                                            \
            cp16(so_ + AT_ARR, g_vt + gv_);                                   \
        } } while (0)

    A_LOAD(0, 0);
    CP_COMMIT();

    for (int kt = 0; kt < nkt; kt++) {
        const int k0 = kt * 64;
        CP_WAIT0();
        __syncthreads();
        if (kt + 1 < nkt) { A_LOAD(kt + 1, (kt + 1) & 1); CP_COMMIT(); }

        const uint32_t bufb = sb + (kt & 1) * AT_BUF;

        if (k0 <= q0 + wm + 15) {
            float s[8][4];
#pragma unroll
            for (int nf = 0; nf < 8; nf++)
#pragma unroll
                for (int r = 0; r < 4; r++) s[nf][r] = 0.f;

#pragma unroll
            for (int ko = 0; ko < 4; ko++) {
#pragma unroll
                for (int p = 0; p < 4; p++) {
                    uint32_t th[4];
                    uint32_t boff = (p * 16 + b_n) * AT_ROW + (ko * 16 + b_kof) * 2;
                    ldm_x4(th, bufb + boff);
                    mma_h(s[2 * p],     qf[ko], th);
                    mma_h(s[2 * p + 1], qf[ko], th + 2);
                }
            }

            const int qa = q0 + wm + (lane >> 2);
            const int qb = qa + 8;
            const bool need_mask = (k0 + 63 > q0 + wm);
#pragma unroll
            for (int nf = 0; nf < 8; nf++) {
                int cg = k0 + nf * 8 + (lane & 3) * 2;
                s[nf][0] *= scale; s[nf][1] *= scale;
                s[nf][2] *= scale; s[nf][3] *= scale;
                if (need_mask) {
                    if (cg > qa)     s[nf][0] = -10000.f;
                    if (cg + 1 > qa) s[nf][1] = -10000.f;
                    if (cg > qb)     s[nf][2] = -10000.f;
                    if (cg + 1 > qb) s[nf][3] = -10000.f;
                }
            }

            float rma = -CUDART_INF_F, rmb = -CUDART_INF_F;
#pragma unroll
            for (int nf = 0; nf < 8; nf++) {
                rma = fmaxf(rma, fmaxf(s[nf][0], s[nf][1]));
                rmb = fmaxf(rmb, fmaxf(s[nf][2], s[nf][3]));
            }
            rma = fmaxf(rma, __shfl_xor_sync(0xffffffffu, rma, 1));
            rma = fmaxf(rma, __shfl_xor_sync(0xffffffffu, rma, 2));
            rmb = fmaxf(rmb, __shfl_xor_sync(0xffffffffu, rmb, 1));
            rmb = fmaxf(rmb, __shfl_xor_sync(0xffffffffu, rmb, 2));
            float nma = fmaxf(m0, rma), nmb = fmaxf(m1, rmb);
            float alpha_a = __expf(m0 - nma), alpha_b = __expf(m1 - nmb);
            m0 = nma; m1 = nmb;

            float rsa = 0.f, rsb = 0.f;
#pragma unroll
            for (int nf = 0; nf < 8; nf++) {
                s[nf][0] = __expf(s[nf][0] - nma);
                s[nf][1] = __expf(s[nf][1] - nma);
                s[nf][2] = __expf(s[nf][2] - nmb);
                s[nf][3] = __expf(s[nf][3] - nmb);
                rsa += s[nf][0] + s[nf][1];
                rsb += s[nf][2] + s[nf][3];
            }
            rsa += __shfl_xor_sync(0xffffffffu, rsa, 1);
            rsa += __shfl_xor_sync(0xffffffffu, rsa, 2);
            rsb += __shfl_xor_sync(0xffffffffu, rsb, 1);
            rsb += __shfl_xor_sync(0xffffffffu, rsb, 2);
            l0 = l0 * alpha_a + rsa;
            l1 = l1 * alpha_b + rsb;

#pragma unroll
            for (int nf = 0; nf < 8; nf++) {
                o[nf][0] *= alpha_a; o[nf][1] *= alpha_a;
                o[nf][2] *= alpha_b; o[nf][3] *= alpha_b;
            }

            uint32_t ph[4][4];
#pragma unroll
            for (int kb = 0; kb < 4; kb++) {
                float* f0 = s[2 * kb];
                float* f1 = s[2 * kb + 1];
                ph[kb][0] = cvt_h2(f0[0], f0[1]);
                ph[kb][1] = cvt_h2(f0[2], f0[3]);
                ph[kb][2] = cvt_h2(f1[0], f1[1]);
                ph[kb][3] = cvt_h2(f1[2], f1[3]);
            }

#pragma unroll
            for (int kb = 0; kb < 4; kb++) {
#pragma unroll
                for (int p = 0; p < 4; p++) {
                    uint32_t th[4];
                    uint32_t boff = (p * 16 + b_n) * AT_ROW + (kb * 16 + b_kof) * 2;
                    ldm_x4(th, bufb + AT_ARR + boff);
                    mma_h(o[2 * p],     ph[kb], th);
                    mma_h(o[2 * p + 1], ph[kb], th + 2);
                }
            }
        }
        __syncthreads();
    }
#undef A_LOAD

    // ---- epilogue: normalize + write fp16 into g_a ----
    float inv_a = 1.0f / l0, inv_b = 1.0f / l1;
    int ra = q0 + wm + (lane >> 2);
    int cq = (lane & 3) * 2;
#pragma unroll
    for (int nf = 0; nf < 8; nf++) {
        int col = h * DHH + nf * 8 + cq;
        float v0 = o[nf][0] * inv_a, v1 = o[nf][1] * inv_a;
        float v2 = o[nf][2] * inv_b, v3 = o[nf][3] * inv_b;
        size_t o0 = ((size_t)b * TT + ra) * DDIM + col;
        size_t o1 = ((size_t)b * TT + ra + 8) * DDIM + col;
        *(uint32_t*)&g_a[o0] = cvt_h2(v0, v1);
        *(uint32_t*)&g_a[o1] = cvt_h2(v2, v3);
    }
}

// ---------------------------------------------------------------------------
// Launch
// ---------------------------------------------------------------------------
extern "C" void kernel_launch(void* const* d_in, const int* in_sizes, int n_in,
                              void* d_out, int out_size)
{
    const float* x  = (const float*)d_in[0];
    const float* wq = (const float*)d_in[2];
    const float* bq = (const float*)d_in[3];
    const float* wk = (const float*)d_in[4];
    const float* bk = (const float*)d_in[5];
    const float* wv = (const float*)d_in[6];
    const float* bv = (const float*)d_in[7];
    const float* wo = (const float*)d_in[8];
    const float* bo = (const float*)d_in[9];
    float* out = (float*)d_out;

    __half *ap, *wp;
    cudaGetSymbolAddress((void**)&ap, g_a);
    cudaGetSymbolAddress((void**)&wp, g_w);

    const size_t WSZ = (size_t)DDIM * DDIM;

    sincos_kernel<<<(TT * 32 + 255) / 256, 256>>>();

    const int n4 = MM * DDIM / 4;
    conv_kernel<<<(n4 + 255) / 256, 256>>>(x, ap, n4);
    convT_kernel<<<dim3(32, 32, 4), dim3(32, 8)>>>(wq, wk, wv, wo);

    cudaFuncSetAttribute(mma_gemm_qkv,
                         cudaFuncAttributeMaxDynamicSharedMemorySize, GEMM_SMEM_EPI);
    cudaFuncSetAttribute(mma_gemm,
                         cudaFuncAttributeMaxDynamicSharedMemorySize, GEMM_SMEM_MAIN);

    // Fused Q/K/V projections: one launch, 768 blocks
    mma_gemm_qkv<<<dim3(DDIM / 128, MM / 128, 3), 256, GEMM_SMEM_EPI>>>(
        ap, bq, bk, bv);

    // flash attention (overwrites g_a with fp16 attention output)
    cudaFuncSetAttribute(attn_mma_kernel,
                         cudaFuncAttributeMaxDynamicSharedMemorySize, ATTN_SMEM);
    attn_mma_kernel<<<dim3(TT / 128, HH, BB), 256, ATTN_SMEM>>>();

    // out-projection -> fp32 output
    mma_gemm<<<dim3(DDIM / 128, MM / 128), 256, GEMM_SMEM_MAIN>>>(
        ap, wp + 3 * WSZ, bo, out);
}

// round 15
// speedup vs baseline: 2.3736x; 1.0637x over previous
#include <cuda_runtime.h>
#include <cuda_fp16.h>
#include <math.h>
#include <math_constants.h>
#include <cstdint>

// Problem constants
#define BB  2
#define TT  2048
#define DDIM 1024
#define HH  16
#define DHH 64
#define MM  (BB*TT)

// ---------------------------------------------------------------------------
// Scratch (device globals)
// ---------------------------------------------------------------------------
__device__ float g_sin[TT * 32];
__device__ float g_cos[TT * 32];

__device__ __half g_a[(size_t)MM * DDIM];        // activations fp16 (x, later attn out)
__device__ __half g_w[(size_t)4 * DDIM * DDIM];  // weights transposed [N,K] fp16
__device__ __half g_qh[(size_t)MM * DDIM];       // q after rope
__device__ __half g_kh[(size_t)MM * DDIM];       // k after rope
__device__ __half g_vt[(size_t)MM * DDIM];       // v transposed [b,h,dh,T]

// ---------------------------------------------------------------------------
// Warp tensor helpers (baseline PTX: ldmatrix + mma.sync + cp.async)
// ---------------------------------------------------------------------------
__device__ __forceinline__ uint32_t smem_u32(const void* p) {
    uint32_t a;
    asm("{ .reg .u64 t; cvta.to.shared.u64 t, %1; cvt.u32.u64 %0, t; }"
        : "=r"(a) : "l"(p));
    return a;
}

__device__ __forceinline__ void ldm_x4(uint32_t* r, uint32_t addr) {
    asm volatile("ldmatrix.sync.aligned.m8n8.x4.shared.b16 {%0,%1,%2,%3}, [%4];"
                 : "=r"(r[0]), "=r"(r[1]), "=r"(r[2]), "=r"(r[3]) : "r"(addr));
}

__device__ __forceinline__ void mma_h(float* c, const uint32_t* a,
                                      const uint32_t* b) {
    asm volatile(
        "mma.sync.aligned.m16n8k16.row.col.f32.f16.f16.f32 "
        "{%0,%1,%2,%3}, {%4,%5,%6,%7}, {%8,%9}, {%0,%1,%2,%3};"
        : "+f"(c[0]), "+f"(c[1]), "+f"(c[2]), "+f"(c[3])
        : "r"(a[0]), "r"(a[1]), "r"(a[2]), "r"(a[3]), "r"(b[0]), "r"(b[1]));
}

__device__ __forceinline__ void cp16(uint32_t dst, const void* src) {
    asm volatile("cp.async.cg.shared.global [%0], [%1], 16;"
                 :: "r"(dst), "l"(src));
}
#define CP_COMMIT() asm volatile("cp.async.commit_group;" ::: "memory")
#define CP_WAIT0()  asm volatile("cp.async.wait_group 0;" ::: "memory")

// pack 2 floats to f16x2: low half = first arg
__device__ __forceinline__ uint32_t cvt_h2(float lo, float hi) {
    uint32_t r;
    asm("cvt.rn.f16x2.f32 %0, %1, %2;" : "=r"(r) : "f"(hi), "f"(lo));
    return r;
}

// ---------------------------------------------------------------------------
// RoPE sin/cos table
// ---------------------------------------------------------------------------
__global__ void sincos_kernel() {
    int idx = blockIdx.x * blockDim.x + threadIdx.x;
    if (idx >= TT * 32) return;
    int t  = idx >> 5;
    int jj = idx & 31;
    double ang = (double)t * pow(10000.0, -2.0 * (double)jj / 64.0);
    g_sin[idx] = (float)sin(ang);
    g_cos[idx] = (float)cos(ang);
}

// ---------------------------------------------------------------------------
// fp32 -> fp16 convert (vectorized)
// ---------------------------------------------------------------------------
__global__ void conv_kernel(const float* __restrict__ src,
                            __half* __restrict__ dst, int n4) {
    int i = blockIdx.x * blockDim.x + threadIdx.x;
    if (i >= n4) return;
    float4 v = ((const float4*)src)[i];
    uint2 o;
    o.x = cvt_h2(v.x, v.y);
    o.y = cvt_h2(v.z, v.w);
    ((uint2*)dst)[i] = o;
}

// fp32 W[K,N] -> fp16 transposed [N,K]; all 4 weights in one launch (z)
__global__ void convT_kernel(const float* __restrict__ w0,
                             const float* __restrict__ w1,
                             const float* __restrict__ w2,
                             const float* __restrict__ w3) {
    __shared__ float tile[32][33];
    int z = blockIdx.z;
    const float* w = (z == 0) ? w0 : (z == 1) ? w1 : (z == 2) ? w2 : w3;
    __half* o = g_w + (size_t)z * DDIM * DDIM;
    int bx = blockIdx.x * 32;
    int by = blockIdx.y * 32;
    int tx = threadIdx.x, ty = threadIdx.y;
#pragma unroll
    for (int i = 0; i < 32; i += 8)
        tile[ty + i][tx] = w[(size_t)(by + ty + i) * DDIM + bx + tx];
    __syncthreads();
#pragma unroll
    for (int i = 0; i < 32; i += 8)
        o[(size_t)(bx + ty + i) * DDIM + by + tx] = __float2half(tile[tx][ty + i]);
}

// ---------------------------------------------------------------------------
// Shared GEMM mainloop: 8 warps, warp tile 64x32, kTile=64 (fewer barriers).
// Row = 64 halves data + 8 pad = 144 bytes (proven conflict-free at 64-wide).
// ---------------------------------------------------------------------------
#define GT_ROW 144       // bytes per smem row (72 halves)
#define GT_ARR 18432     // bytes per tile array (128*144)
#define GT_BUF 36864     // bytes per stage (A + B)
#define GEMM_SMEM (2 * GT_BUF)   // 73728; fp32 epilogue staging (66048) fits

#define G_LOAD(kt, buf) do {                                                  \
        int k0_ = (kt) * 64;                                                  \
        _Pragma("unroll")                                                     \
        for (int q_ = 0; q_ < 4; q_++) {                                      \
            int row_ = q_ * 32 + ld_row;                                      \
            size_t ga_ = (size_t)(bm + row_) * DDIM + k0_ + ld_cg;            \
            size_t gb_ = (size_t)(bn + row_) * DDIM + k0_ + ld_cg;            \
            uint32_t so_ = sb + (buf) * GT_BUF + row_ * GT_ROW + ld_cg * 2;   \
            cp16(so_, A + ga_);                                               \
            cp16(so_ + GT_ARR, Bw + gb_);                                     \
        } } while (0)

#define G_MAINLOOP()                                                          \
    G_LOAD(0, 0);                                                             \
    CP_COMMIT();                                                              \
    for (int kt = 0; kt < 16; kt++) {                                         \
        CP_WAIT0();                                                           \
        __syncthreads();                                                      \
        if (kt + 1 < 16) { G_LOAD(kt + 1, (kt + 1) & 1); CP_COMMIT(); }       \
        const uint32_t bufb = sb + (kt & 1) * GT_BUF;                         \
        _Pragma("unroll")                                                     \
        for (int ko = 0; ko < 64; ko += 16) {                                 \
            uint32_t bfr[4][2];                                               \
            _Pragma("unroll")                                                 \
            for (int p = 0; p < 2; p++) {                                     \
                uint32_t t4[4];                                               \
                uint32_t boff = (wn + p * 16 + b_n) * GT_ROW + (ko + b_kof) * 2; \
                ldm_x4(t4, bufb + GT_ARR + boff);                             \
                bfr[p * 2][0] = t4[0]; bfr[p * 2][1] = t4[1];                 \
                bfr[p * 2 + 1][0] = t4[2]; bfr[p * 2 + 1][1] = t4[3];         \
            }                                                                 \
            _Pragma("unroll")                                                 \
            for (int mf = 0; mf < 4; mf++) {                                  \
                uint32_t ar[4];                                               \
                uint32_t aoff = (wm + mf * 16 + a_row) * GT_ROW + (ko + a_kof) * 2; \
                ldm_x4(ar, bufb + aoff);                                      \
                _Pragma("unroll")                                             \
                for (int nf = 0; nf < 4; nf++)                                \
                    mma_h(acc[mf][nf], ar, bfr[nf]);                          \
            }                                                                 \
        }                                                                     \
        __syncthreads();                                                      \
    }

#define G_PROLOG_BODY()                                                       \
    extern __shared__ char gsm[];                                             \
    const uint32_t sb = smem_u32(gsm);                                        \
    const int tid = threadIdx.x;                                              \
    const int lane = tid & 31;                                                \
    const int wid = tid >> 5;                                                 \
    const int wm = (wid & 1) * 64;                                            \
    const int wn = (wid >> 1) * 32;                                           \
    const int bn = blockIdx.x * 128;                                          \
    const int bm = blockIdx.y * 128;                                          \
    float acc[4][4][4];                                                       \
    _Pragma("unroll")                                                         \
    for (int i = 0; i < 4; i++)                                               \
        _Pragma("unroll")                                                     \
        for (int j = 0; j < 4; j++)                                           \
            _Pragma("unroll")                                                 \
            for (int r = 0; r < 4; r++) acc[i][j][r] = 0.f;                   \
    const int a_row = lane & 15;                                              \
    const int a_kof = (lane >> 4) << 3;                                       \
    const int b_n   = (lane & 7) + ((lane >> 4) << 3);                        \
    const int b_kof = ((lane >> 3) & 1) << 3;                                 \
    const int ld_row = tid >> 3;                                              \
    const int ld_cg  = (tid & 7) * 8;

// Store acc + bias into fp32 staging smem [128][129]
#define G_STAGE_SMEM()                                                        \
    float* Ssm = (float*)gsm;                                                 \
    {                                                                         \
        const int qr = lane >> 2;                                             \
        const int qc = (lane & 3) * 2;                                        \
        _Pragma("unroll")                                                     \
        for (int mf = 0; mf < 4; mf++) {                                      \
            _Pragma("unroll")                                                 \
            for (int nf = 0; nf < 4; nf++) {                                  \
                int row = wm + mf * 16 + qr;                                  \
                int col = wn + nf * 8 + qc;                                   \
                float b0 = bias[bn + col], b1 = bias[bn + col + 1];           \
                Ssm[row * 129 + col]     = acc[mf][nf][0] + b0;               \
                Ssm[row * 129 + col + 1] = acc[mf][nf][1] + b1;               \
                Ssm[(row + 8) * 129 + col]     = acc[mf][nf][2] + b0;         \
                Ssm[(row + 8) * 129 + col + 1] = acc[mf][nf][3] + b1;         \
            }                                                                 \
        }                                                                     \
    }                                                                         \
    __syncthreads();

// ---------------------------------------------------------------------------
// Fused QKV projection: grid (8, 32, 3); z selects weight slab + epilogue.
// ---------------------------------------------------------------------------
__global__ void __launch_bounds__(256, 2) mma_gemm_qkv(
    const __half* __restrict__ A,
    const float* __restrict__ bqv, const float* __restrict__ bkv,
    const float* __restrict__ bvv)
{
    const int z = blockIdx.z;
    const __half* Bw = g_w + (size_t)z * DDIM * DDIM;
    const float* bias = (z == 0) ? bqv : (z == 1) ? bkv : bvv;

    G_PROLOG_BODY();
    G_MAINLOOP();
    G_STAGE_SMEM();

    if (z < 2) {
        // ---- rope epilogue -> g_qh / g_kh ----
        __half* O = (z == 0) ? g_qh : g_kh;
        for (int p = tid; p < 8192; p += 256) {
            int j  = p & 31;
            int hh = (p >> 5) & 1;
            int m  = p >> 6;
            int gm = bm + m;
            int t  = gm & (TT - 1);
            int cb = hh * 64;
            float a  = Ssm[m * 129 + cb + j];
            float bv = Ssm[m * 129 + cb + j + 32];
            int jj = j >> 1;
            float c1 = g_cos[t * 32 + jj],      s1 = g_sin[t * 32 + jj];
            float c2 = g_cos[t * 32 + jj + 16], s2 = g_sin[t * 32 + jj + 16];
            float o0 = a * c1 - bv * s1;
            float o1 = bv * c2 + a * s2;
            size_t off = (size_t)gm * DDIM + bn + cb + j;
            O[off]      = __float2half(o0);
            O[off + 32] = __float2half(o1);
        }
    } else {
        // ---- vt epilogue: transpose -> g_vt[b,h,dh,T] ----
        const int bq_ = bm >> 11;
        const int tm  = bm & (TT - 1);
#pragma unroll
        for (int ci = 0; ci < 16; ci++) {
            int c = wid + ci * 8;
            int gcol = bn + c;
            int hh = gcol >> 6, d = gcol & 63;
            size_t obase = ((size_t)(bq_ * HH + hh) * DHH + d) * TT + tm;
#pragma unroll
            for (int rj = 0; rj < 4; rj++) {
                int row = lane + rj * 32;
                g_vt[obase + row] = __float2half(Ssm[row * 129 + c]);
            }
        }
    }
}

// ---------------------------------------------------------------------------
// Plain GEMM: fp32 output + bias (out-projection)
// ---------------------------------------------------------------------------
__global__ void __launch_bounds__(256, 2) mma_gemm(
    const __half* __restrict__ A, const __half* __restrict__ Bw,
    const float* __restrict__ bias, float* __restrict__ C)
{
    G_PROLOG_BODY();
    G_MAINLOOP();

    const int qr = lane >> 2;
    const int qc = (lane & 3) * 2;
#pragma unroll
    for (int mf = 0; mf < 4; mf++) {
#pragma unroll
        for (int nf = 0; nf < 4; nf++) {
            int col = bn + wn + nf * 8 + qc;
            float b0 = bias[col], b1 = bias[col + 1];
            int r0 = bm + wm + mf * 16 + qr;
            float2 v0 = {acc[mf][nf][0] + b0, acc[mf][nf][1] + b1};
            float2 v1 = {acc[mf][nf][2] + b0, acc[mf][nf][3] + b1};
            *(float2*)&C[(size_t)r0 * DDIM + col] = v0;
            *(float2*)&C[(size_t)(r0 + 8) * DDIM + col] = v1;
        }
    }
}

// ---------------------------------------------------------------------------
// Flash attention, fp16 single-pass, cp.async double-buffered K/V staging.
// ---------------------------------------------------------------------------
#define AT_ROW 144
#define AT_ARR 9216
#define AT_BUF 18432
#define ATTN_SMEM (2 * AT_BUF)

__global__ void __launch_bounds__(256) attn_mma_kernel() {
    extern __shared__ char gsm[];
    const uint32_t sb = smem_u32(gsm);

    const int q0 = (gridDim.x - 1 - blockIdx.x) * 128;  // heavy blocks first
    const int h  = blockIdx.y;
    const int b  = blockIdx.z;
    const int tid = threadIdx.x;
    const int lane = tid & 31;
    const int wid = tid >> 5;
    const int wm = wid * 16;

    const size_t base_qk = (size_t)b * TT * DDIM + (size_t)h * DHH;
    const size_t base_vt = ((size_t)(b * HH + h)) * DHH * TT;

    const int a_row = lane & 15;
    const int a_kof = (lane >> 4) << 3;
    const int b_n   = (lane & 7) + ((lane >> 4) << 3);
    const int b_kof = ((lane >> 3) & 1) << 3;

    // ---- stage Q tile, load Q frags to registers ----
    for (int i = tid; i < 128 * 8; i += 256) {
        int r = i >> 3, c = (i & 7) * 8;
        size_t g = base_qk + (size_t)(q0 + r) * DDIM + c;
        *(uint4*)(gsm + r * AT_ROW + c * 2) = *(const uint4*)&g_qh[g];
    }
    __syncthreads();

    uint32_t qf[4][4];
#pragma unroll
    for (int ko = 0; ko < 4; ko++) {
        uint32_t aoff = (wm + a_row) * AT_ROW + (ko * 16 + a_kof) * 2;
        ldm_x4(qf[ko], sb + aoff);
    }
    __syncthreads();

    float m0 = -CUDART_INF_F, m1 = -CUDART_INF_F;
    float l0 = 0.f, l1 = 0.f;
    float o[8][4];
#pragma unroll
    for (int nf = 0; nf < 8; nf++)
#pragma unroll
        for (int r = 0; r < 4; r++) o[nf][r] = 0.f;

    const int nkt = q0 / 64 + 2;
    const float scale = 0.125f;

#define A_LOAD(kt, buf) do {                                                  \
        int k0_ = (kt) * 64;                                                  \
        _Pragma("unroll")                                                     \
        for (int i = tid; i < 512; i += 256) {                                \
            int r_ = i >> 3, c_ = (i & 7) * 8;                                \
            uint32_t so_ = sb + (buf) * AT_BUF + r_ * AT_ROW + c_ * 2;        \
            size_t gk_ = base_qk + (size_t)(k0_ + r_) * DDIM + c_;            \
            size_t gv_ = base_vt + (size_t)r_ * TT + k0_ + c_;                \
            cp16(so_, g_kh + gk_);                                            \
            cp16(so_ + AT_ARR, g_vt + gv_);                                   \
        } } while (0)

    A_LOAD(0, 0);
    CP_COMMIT();

    for (int kt = 0; kt < nkt; kt++) {
        const int k0 = kt * 64;
        CP_WAIT0();
        __syncthreads();
        if (kt + 1 < nkt) { A_LOAD(kt + 1, (kt + 1) & 1); CP_COMMIT(); }

        const uint32_t bufb = sb + (kt & 1) * AT_BUF;

        if (k0 <= q0 + wm + 15) {
            float s[8][4];
#pragma unroll
            for (int nf = 0; nf < 8; nf++)
#pragma unroll
                for (int r = 0; r < 4; r++) s[nf][r] = 0.f;

#pragma unroll
            for (int ko = 0; ko < 4; ko++) {
#pragma unroll
                for (int p = 0; p < 4; p++) {
                    uint32_t th[4];
                    uint32_t boff = (p * 16 + b_n) * AT_ROW + (ko * 16 + b_kof) * 2;
                    ldm_x4(th, bufb + boff);
                    mma_h(s[2 * p],     qf[ko], th);
                    mma_h(s[2 * p + 1], qf[ko], th + 2);
                }
            }

            const int qa = q0 + wm + (lane >> 2);
            const int qb = qa + 8;
            const bool need_mask = (k0 + 63 > q0 + wm);
#pragma unroll
            for (int nf = 0; nf < 8; nf++) {
                int cg = k0 + nf * 8 + (lane & 3) * 2;
                s[nf][0] *= scale; s[nf][1] *= scale;
                s[nf][2] *= scale; s[nf][3] *= scale;
                if (need_mask) {
                    if (cg > qa)     s[nf][0] = -10000.f;
                    if (cg + 1 > qa) s[nf][1] = -10000.f;
                    if (cg > qb)     s[nf][2] = -10000.f;
                    if (cg + 1 > qb) s[nf][3] = -10000.f;
                }
            }

            float rma = -CUDART_INF_F, rmb = -CUDART_INF_F;
#pragma unroll
            for (int nf = 0; nf < 8; nf++) {
                rma = fmaxf(rma, fmaxf(s[nf][0], s[nf][1]));
                rmb = fmaxf(rmb, fmaxf(s[nf][2], s[nf][3]));
            }
            rma = fmaxf(rma, __shfl_xor_sync(0xffffffffu, rma, 1));
            rma = fmaxf(rma, __shfl_xor_sync(0xffffffffu, rma, 2));
            rmb = fmaxf(rmb, __shfl_xor_sync(0xffffffffu, rmb, 1));
            rmb = fmaxf(rmb, __shfl_xor_sync(0xffffffffu, rmb, 2));
            float nma = fmaxf(m0, rma), nmb = fmaxf(m1, rmb);
            float alpha_a = __expf(m0 - nma), alpha_b = __expf(m1 - nmb);
            m0 = nma; m1 = nmb;

            float rsa = 0.f, rsb = 0.f;
#pragma unroll
            for (int nf = 0; nf < 8; nf++) {
                s[nf][0] = __expf(s[nf][0] - nma);
                s[nf][1] = __expf(s[nf][1] - nma);
                s[nf][2] = __expf(s[nf][2] - nmb);
                s[nf][3] = __expf(s[nf][3] - nmb);
                rsa += s[nf][0] + s[nf][1];
                rsb += s[nf][2] + s[nf][3];
            }
            rsa += __shfl_xor_sync(0xffffffffu, rsa, 1);
            rsa += __shfl_xor_sync(0xffffffffu, rsa, 2);
            rsb += __shfl_xor_sync(0xffffffffu, rsb, 1);
            rsb += __shfl_xor_sync(0xffffffffu, rsb, 2);
            l0 = l0 * alpha_a + rsa;
            l1 = l1 * alpha_b + rsb;

#pragma unroll
            for (int nf = 0; nf < 8; nf++) {
                o[nf][0] *= alpha_a; o[nf][1] *= alpha_a;
                o[nf][2] *= alpha_b; o[nf][3] *= alpha_b;
            }

            uint32_t ph[4][4];
#pragma unroll
            for (int kb = 0; kb < 4; kb++) {
                float* f0 = s[2 * kb];
                float* f1 = s[2 * kb + 1];
                ph[kb][0] = cvt_h2(f0[0], f0[1]);
                ph[kb][1] = cvt_h2(f0[2], f0[3]);
                ph[kb][2] = cvt_h2(f1[0], f1[1]);
                ph[kb][3] = cvt_h2(f1[2], f1[3]);
            }

#pragma unroll
            for (int kb = 0; kb < 4; kb++) {
#pragma unroll
                for (int p = 0; p < 4; p++) {
                    uint32_t th[4];
                    uint32_t boff = (p * 16 + b_n) * AT_ROW + (kb * 16 + b_kof) * 2;
                    ldm_x4(th, bufb + AT_ARR + boff);
                    mma_h(o[2 * p],     ph[kb], th);
                    mma_h(o[2 * p + 1], ph[kb], th + 2);
                }
            }
        }
        __syncthreads();
    }
#undef A_LOAD

    // ---- epilogue: normalize + write fp16 into g_a ----
    float inv_a = 1.0f / l0, inv_b = 1.0f / l1;
    int ra = q0 + wm + (lane >> 2);
    int cq = (lane & 3) * 2;
#pragma unroll
    for (int nf = 0; nf < 8; nf++) {
        int col = h * DHH + nf * 8 + cq;
        float v0 = o[nf][0] * inv_a, v1 = o[nf][1] * inv_a;
        float v2 = o[nf][2] * inv_b, v3 = o[nf][3] * inv_b;
        size_t o0 = ((size_t)b * TT + ra) * DDIM + col;
        size_t o1 = ((size_t)b * TT + ra + 8) * DDIM + col;
        *(uint32_t*)&g_a[o0] = cvt_h2(v0, v1);
        *(uint32_t*)&g_a[o1] = cvt_h2(v2, v3);
    }
}

// ---------------------------------------------------------------------------
// Launch
// ---------------------------------------------------------------------------
extern "C" void kernel_launch(void* const* d_in, const int* in_sizes, int n_in,
                              void* d_out, int out_size)
{
    const float* x  = (const float*)d_in[0];
    const float* wq = (const float*)d_in[2];
    const float* bq = (const float*)d_in[3];
    const float* wk = (const float*)d_in[4];
    const float* bk = (const float*)d_in[5];
    const float* wv = (const float*)d_in[6];
    const float* bv = (const float*)d_in[7];
    const float* wo = (const float*)d_in[8];
    const float* bo = (const float*)d_in[9];
    float* out = (float*)d_out;

    __half *ap, *wp;
    cudaGetSymbolAddress((void**)&ap, g_a);
    cudaGetSymbolAddress((void**)&wp, g_w);

    const size_t WSZ = (size_t)DDIM * DDIM;

    sincos_kernel<<<(TT * 32 + 255) / 256, 256>>>();

    const int n4 = MM * DDIM / 4;
    conv_kernel<<<(n4 + 255) / 256, 256>>>(x, ap, n4);
    convT_kernel<<<dim3(32, 32, 4), dim3(32, 8)>>>(wq, wk, wv, wo);

    cudaFuncSetAttribute(mma_gemm_qkv,
                         cudaFuncAttributeMaxDynamicSharedMemorySize, GEMM_SMEM);
    cudaFuncSetAttribute(mma_gemm,
                         cudaFuncAttributeMaxDynamicSharedMemorySize, GEMM_SMEM);

    // Fused Q/K/V projections: one launch, 768 blocks
    mma_gemm_qkv<<<dim3(DDIM / 128, MM / 128, 3), 256, GEMM_SMEM>>>(
        ap, bq, bk, bv);

    // flash attention (overwrites g_a with fp16 attention output)
    cudaFuncSetAttribute(attn_mma_kernel,
                         cudaFuncAttributeMaxDynamicSharedMemorySize, ATTN_SMEM);
    attn_mma_kernel<<<dim3(TT / 128, HH, BB), 256, ATTN_SMEM>>>();

    // out-projection -> fp32 output
    mma_gemm<<<dim3(DDIM / 128, MM / 128), 256, GEMM_SMEM>>>(
        ap, wp + 3 * WSZ, bo, out);
}